// round 8
// baseline (speedup 1.0000x reference)
#include <cuda_runtime.h>
#include <math.h>
#include <stdint.h>

#define MTOT 131072
#define TPB  256
#define TOK  128
#define NBLK (MTOT / TOK)

#define XHS 144   // x|h tile row stride; %32==16 -> conflict-free packed LDS.128 A-loads
#define WS  80    // packed K=64 weight row stride
#define FCS 72    // stage-A per-k-half weight row stride (64 data + 8 pad)

// smem float offsets
#define SW_OFF    0         // buf0 = +0 (5184), buf1 = +5184 (3840)
#define BUF1      5184
#define SXH_OFF   9024
#define SGATE_OFF 27456     // [128][8]
#define SMEMF     28480     // 113,920 B -> 2 CTAs/SM

// packed-weight global offsets (floats)
#define GW_FC   0           // 2 k-halves x [72][72] (fc 64 rows + gate 8 rows)
#define GW_GRU  10368       // 4 chunks x (ih [48][80] + hh [48][80])
#define GW_E1   41088       // [8][64][80]
#define GW_E2   82048       // [8][32][80]
#define GW_TOT  102528

__device__ __align__(16) float g_wp[GW_TOT];

__device__ __forceinline__ float f2tf_f(float f) {
    uint32_t u; asm("cvt.rna.tf32.f32 %0, %1;" : "=r"(u) : "f"(f));
    return __uint_as_float(u);
}
__device__ __forceinline__ float sig_(float v) { return 1.0f / (1.0f + __expf(-v)); }
// stage-A pairing: (k, k+4) adjacent within a k-half
__device__ __forceinline__ int packpos(int k) {
    return ((k >> 3) << 3) + ((k & 3) << 1) + ((k >> 2) & 1);
}
// 16-group pairing: position 16g+4t+i holds k = 16g + t + 4i
__device__ __forceinline__ int pp2(int k) {
    return ((k >> 4) << 4) + ((k & 3) << 2) + ((k & 15) >> 2);
}

__device__ __forceinline__ void cp16(float* dst, const float* src) {
    uint32_t d = (uint32_t)__cvta_generic_to_shared(dst);
    asm volatile("cp.async.cg.shared.global [%0], [%1], 16;" :: "r"(d), "l"(src));
}
__device__ __forceinline__ void stage_async(float* dst, const float* src, int n, int t) {
    for (int i = t * 4; i < n; i += TPB * 4) cp16(dst + i, src + i);
}
#define CP_COMMIT asm volatile("cp.async.commit_group;")
#define CP_WAIT0  asm volatile("cp.async.wait_group 0;")
#define PAIR_BAR  asm volatile("bar.sync %0, 64;" :: "r"(p + 1) : "memory")

__device__ __forceinline__ void mma8(float* d,
    uint32_t a0, uint32_t a1, uint32_t a2, uint32_t a3, uint32_t b0, uint32_t b1)
{
    asm volatile(
        "mma.sync.aligned.m16n8k8.row.col.f32.tf32.tf32.f32 "
        "{%0,%1,%2,%3}, {%4,%5,%6,%7}, {%8,%9}, {%0,%1,%2,%3};"
        : "+f"(d[0]), "+f"(d[1]), "+f"(d[2]), "+f"(d[3])
        : "r"(a0), "r"(a1), "r"(a2), "r"(a3), "r"(b0), "r"(b1));
}

// scalar A-fragments for two m16 stripes (natural-layout operand), one k-step
#define LOAD_A8(ptr, stride)                                            \
    uint32_t a0 = __float_as_uint((ptr)[tig]);                          \
    uint32_t a2 = __float_as_uint((ptr)[tig + 4]);                      \
    uint32_t a1 = __float_as_uint((ptr)[8 * (stride) + tig]);           \
    uint32_t a3 = __float_as_uint((ptr)[8 * (stride) + tig + 4]);       \
    uint32_t a4 = __float_as_uint((ptr)[16 * (stride) + tig]);          \
    uint32_t a6 = __float_as_uint((ptr)[16 * (stride) + tig + 4]);      \
    uint32_t a5 = __float_as_uint((ptr)[24 * (stride) + tig]);          \
    uint32_t a7 = __float_as_uint((ptr)[24 * (stride) + tig + 4]);

#define MMA2P(acc, b0v, b1v)                            \
    mma8((acc)[0], a0, a1, a2, a3, (b0v), (b1v));       \
    mma8((acc)[1], a4, a5, a6, a7, (b0v), (b1v));

// packed A-fragments: 4 LDS.128 cover BOTH k-steps of a 16-k group, both stripes
#define LOAD_PA(base)                                                   \
    uint4 v0 = *(const uint4*)(base);                                   \
    uint4 v1 = *(const uint4*)((base) + 8 * XHS);                       \
    uint4 v2 = *(const uint4*)((base) + 16 * XHS);                      \
    uint4 v3 = *(const uint4*)((base) + 24 * XHS);

#define MMA2PE(acc, b0v, b1v)                                           \
    mma8((acc)[0], v0.x, v1.x, v0.y, v1.y, (b0v), (b1v));               \
    mma8((acc)[1], v2.x, v3.x, v2.y, v3.y, (b0v), (b1v));
#define MMA2PO(acc, b0v, b1v)                                           \
    mma8((acc)[0], v0.z, v1.z, v0.w, v1.w, (b0v), (b1v));               \
    mma8((acc)[1], v2.z, v3.z, v2.w, v3.w, (b0v), (b1v));

// ---------------- prep: pack + tf32-convert all weights once ----------------
__global__ void prep_pack(const float* __restrict__ fc_w, const float* __restrict__ gate_w,
                          const float* __restrict__ w_ih, const float* __restrict__ w_hh,
                          const float* __restrict__ e_w1, const float* __restrict__ e_w2)
{
    int tid = blockIdx.x * blockDim.x + threadIdx.x;
    int nth = gridDim.x * blockDim.x;
    for (int i = tid; i < 72 * 128; i += nth) {
        int j = i >> 7, k = i & 127;
        int kh = k >> 6, kl = k & 63;
        float v = (j < 64) ? __ldg(fc_w + j * 128 + k) : __ldg(gate_w + (j - 64) * 128 + k);
        g_wp[GW_FC + kh * 5184 + j * FCS + packpos(kl)] = f2tf_f(v);
    }
    for (int i = tid; i < 192 * 64; i += nth) {
        int R = i >> 6, k = i & 63;
        int c = (R & 63) >> 4, grp = R >> 6, lr = grp * 16 + (R & 15);
        int d = GW_GRU + c * 7680 + lr * WS + pp2(k);
        g_wp[d]        = f2tf_f(__ldg(w_ih + i));
        g_wp[d + 3840] = f2tf_f(__ldg(w_hh + i));
    }
    for (int i = tid; i < 8 * 64 * 64; i += nth) {
        int n = i >> 12, r = (i >> 6) & 63, k = i & 63;
        g_wp[GW_E1 + n * 5120 + r * WS + pp2(k)] = f2tf_f(__ldg(e_w1 + i));
    }
    for (int i = tid; i < 8 * 32 * 64; i += nth) {
        int n = i >> 11, r = (i >> 6) & 31, k = i & 63;
        g_wp[GW_E2 + n * 2560 + r * WS + pp2(k)] = f2tf_f(__ldg(e_w2 + i));
    }
}

// ---------------- main: 8 warps, paired 32-row stripes, packed-A hot loops ----------------
__global__ void __launch_bounds__(TPB, 2) msp_main(
    const float* __restrict__ xin,  const float* __restrict__ hin,
    const float* __restrict__ fc_b,
    const float* __restrict__ b_ih, const float* __restrict__ b_hh,
    const float* __restrict__ e_b1, const float* __restrict__ e_b2,
    const float* __restrict__ gate_b,
    float* __restrict__ out)
{
    extern __shared__ float sm[];
    float* s_w    = sm + SW_OFF;
    float* s_xh   = sm + SXH_OFF;
    float* s_gate = sm + SGATE_OFF;

    const int t = threadIdx.x, lane = t & 31, wid = t >> 5;
    const int gid = lane >> 2, tig = lane & 3;
    const int p = wid >> 1, half = wid & 1;
    const int r0 = p << 5, base = blockIdx.x * TOK;
    const int row0 = r0 + gid;   // stripe rows: row0, +8, +16, +24

    // ---- prologue: FC k-half0 -> buf0, GRU-ih0 -> buf1, h_in (natural cols 64..127) ----
    stage_async(s_w, g_wp + GW_FC, 5184, t);
    stage_async(s_w + BUF1, g_wp + GW_GRU, 3840, t);
    for (int i = t; i < TOK * 16; i += TPB) {
        int r = i >> 4, c = i & 15;
        cp16(s_xh + r * XHS + 64 + c * 4, hin + (size_t)(base + r) * 64 + c * 4);
    }
    CP_COMMIT;
    {   // x_in k-half0 (RNA tf32, natural) -> cols 0..63
        const float4* xsrc = (const float4*)xin;
        for (int i = t; i < TOK * 16; i += TPB) {
            int r = i >> 4, c = i & 15;
            float4 v = xsrc[(size_t)(base + r) * 32 + c];
            v.x = f2tf_f(v.x); v.y = f2tf_f(v.y); v.z = f2tf_f(v.z); v.w = f2tf_f(v.w);
            *(float4*)(s_xh + r * XHS + c * 4) = v;
        }
    }
    CP_WAIT0;
    __syncthreads();

    // ---- Stage A: x = relu(x_in @ fc_w^T + b); half1 warps also compute gate ----
    {
        float accF[4][2][4], accG[2][4];
        #pragma unroll
        for (int nt = 0; nt < 4; ++nt) {
            int cb = half * 32 + nt * 8 + 2 * tig;
            float b0 = __ldg(fc_b + cb), b1 = __ldg(fc_b + cb + 1);
            #pragma unroll
            for (int s = 0; s < 2; ++s) {
                accF[nt][s][0] = b0; accF[nt][s][1] = b1;
                accF[nt][s][2] = b0; accF[nt][s][3] = b1;
            }
        }
        {
            float g0 = __ldg(gate_b + 2 * tig), g1 = __ldg(gate_b + 2 * tig + 1);
            #pragma unroll
            for (int s = 0; s < 2; ++s) {
                accG[s][0] = g0; accG[s][1] = g1; accG[s][2] = g0; accG[s][3] = g1;
            }
        }
        #pragma unroll
        for (int kh = 0; kh < 2; ++kh) {
            if (kh == 1) {
                __syncthreads();   // buf0 (FC-h0) + x_in h0 reads done
                stage_async(s_w, g_wp + GW_FC + 5184, 5184, t);   // FC k-half1 -> buf0
                CP_COMMIT;
                const float4* xsrc = (const float4*)xin;
                for (int i = t; i < TOK * 16; i += TPB) {
                    int r = i >> 4, c = i & 15;
                    float4 v = xsrc[(size_t)(base + r) * 32 + 16 + c];
                    v.x = f2tf_f(v.x); v.y = f2tf_f(v.y); v.z = f2tf_f(v.z); v.w = f2tf_f(v.w);
                    *(float4*)(s_xh + r * XHS + c * 4) = v;
                }
                CP_WAIT0;
                __syncthreads();
            }
            #pragma unroll
            for (int ks = 0; ks < 8; ++ks) {
                const float* ap = s_xh + row0 * XHS + ks * 8;
                LOAD_A8(ap, XHS)
                const int kb = ks * 8 + 2 * tig;
                #pragma unroll
                for (int nt = 0; nt < 4; ++nt) {
                    uint2 bv = *(const uint2*)(s_w + (half * 32 + nt * 8 + gid) * FCS + kb);
                    MMA2P(accF[nt], bv.x, bv.y)
                }
                if (half) {
                    uint2 gv = *(const uint2*)(s_w + (64 + gid) * FCS + kb);
                    MMA2P(accG, gv.x, gv.y)
                }
            }
        }
        PAIR_BAR;   // partner done reading x_in rows of this stripe before packed overwrite
        #pragma unroll
        for (int nt = 0; nt < 4; ++nt) {
            int c0 = half * 32 + nt * 8 + 2 * tig;
            int q0 = pp2(c0);   // c0 even -> pp2(c0+1) == q0+4
            #pragma unroll
            for (int s = 0; s < 2; ++s) {
                int ra = row0 + s * 16, rb = ra + 8;
                s_xh[ra * XHS + q0]     = f2tf_f(fmaxf(accF[nt][s][0], 0.f));
                s_xh[ra * XHS + q0 + 4] = f2tf_f(fmaxf(accF[nt][s][1], 0.f));
                s_xh[rb * XHS + q0]     = f2tf_f(fmaxf(accF[nt][s][2], 0.f));
                s_xh[rb * XHS + q0 + 4] = f2tf_f(fmaxf(accF[nt][s][3], 0.f));
            }
        }
        if (half) {
            #pragma unroll
            for (int s = 0; s < 2; ++s) {
                int ra = row0 + s * 16, rb = ra + 8;
                s_gate[ra * 8 + 2 * tig]     = sig_(accG[s][0]);
                s_gate[ra * 8 + 2 * tig + 1] = sig_(accG[s][1]);
                s_gate[rb * 8 + 2 * tig]     = sig_(accG[s][2]);
                s_gate[rb * 8 + 2 * tig + 1] = sig_(accG[s][3]);
            }
        }
    }
    __syncthreads();   // stage-A weight reads done; buf0 free

    // ---- GRU: 4 chunks; ih in buf1 (prefetched), hh in buf0 ----
    float hpark[24];
    #pragma unroll 1
    for (int c = 0; c < 4; ++c) {
        stage_async(s_w, g_wp + GW_GRU + c * 7680 + 3840, 3840, t);   // hh(c) -> buf0
        CP_COMMIT;

        float ar[2][4], az[2][4], ani[2][4], anh[2][4];
        {
            int j0 = c * 16 + half * 8 + 2 * tig;
            float v0 = __ldg(b_ih + j0) + __ldg(b_hh + j0);
            float v1 = __ldg(b_ih + j0 + 1) + __ldg(b_hh + j0 + 1);
            float z0 = __ldg(b_ih + 64 + j0) + __ldg(b_hh + 64 + j0);
            float z1 = __ldg(b_ih + 64 + j0 + 1) + __ldg(b_hh + 64 + j0 + 1);
            float n0 = __ldg(b_ih + 128 + j0), n1 = __ldg(b_ih + 128 + j0 + 1);
            float m0 = __ldg(b_hh + 128 + j0), m1 = __ldg(b_hh + 128 + j0 + 1);
            #pragma unroll
            for (int s = 0; s < 2; ++s) {
                ar[s][0] = v0; ar[s][1] = v1; ar[s][2] = v0; ar[s][3] = v1;
                az[s][0] = z0; az[s][1] = z1; az[s][2] = z0; az[s][3] = z1;
                ani[s][0] = n0; ani[s][1] = n1; ani[s][2] = n0; ani[s][3] = n1;
                anh[s][0] = m0; anh[s][1] = m1; anh[s][2] = m0; anh[s][3] = m1;
            }
        }
        // x-part: A = x (packed, cols 0..63), B = ih(c) in buf1
        #pragma unroll
        for (int kp = 0; kp < 4; ++kp) {
            const int kc = kp * 16 + 4 * tig;
            uint4 br = *(const uint4*)(s_w + BUF1 + (half * 8 + gid) * WS + kc);
            uint4 bz = *(const uint4*)(s_w + BUF1 + (16 + half * 8 + gid) * WS + kc);
            uint4 bn = *(const uint4*)(s_w + BUF1 + (32 + half * 8 + gid) * WS + kc);
            LOAD_PA(s_xh + row0 * XHS + kc)
            MMA2PE(ar, br.x, br.y)  MMA2PE(az, bz.x, bz.y)  MMA2PE(ani, bn.x, bn.y)
            MMA2PO(ar, br.z, br.w)  MMA2PO(az, bz.z, bz.w)  MMA2PO(ani, bn.z, bn.w)
        }
        CP_WAIT0;
        __syncthreads();   // hh(c) arrived; buf1 reads done

        if (c < 3) {
            stage_async(s_w + BUF1, g_wp + GW_GRU + (c + 1) * 7680, 3840, t);  // ih(c+1)
            CP_COMMIT;
        }
        // h-part: A = h_in (natural, cols 64..127), B = hh(c) in buf0
        #pragma unroll
        for (int kp = 0; kp < 4; ++kp) {
            const int kc = kp * 16 + 4 * tig;
            uint4 br = *(const uint4*)(s_w + (half * 8 + gid) * WS + kc);
            uint4 bz = *(const uint4*)(s_w + (16 + half * 8 + gid) * WS + kc);
            uint4 bn = *(const uint4*)(s_w + (32 + half * 8 + gid) * WS + kc);
            {
                const float* ap = s_xh + row0 * XHS + 64 + kp * 16;
                LOAD_A8(ap, XHS)
                MMA2P(ar, br.x, br.y)  MMA2P(az, bz.x, bz.y)  MMA2P(anh, bn.x, bn.y)
            }
            {
                const float* ap = s_xh + row0 * XHS + 64 + kp * 16 + 8;
                LOAD_A8(ap, XHS)
                MMA2P(ar, br.z, br.w)  MMA2P(az, bz.z, bz.w)  MMA2P(anh, bn.z, bn.w)
            }
        }
        if (c == 3) { PAIR_BAR; }  // partner finished x(packed) + h_in reads
        #pragma unroll
        for (int s = 0; s < 2; ++s) {
            #pragma unroll
            for (int e = 0; e < 4; ++e) {
                int row = row0 + s * 16 + ((e & 2) ? 8 : 0);
                int j = c * 16 + half * 8 + 2 * tig + (e & 1);
                float rr = sig_(ar[s][e]);
                float zz = sig_(az[s][e]);
                float nn = tanhf(fmaf(rr, anh[s][e], ani[s][e]));
                float hp = s_xh[row * XHS + 64 + j];     // h_in natural
                float hh = fmaf(zz, hp - nn, nn);
                if (c < 3) hpark[c * 8 + s * 4 + e] = hh;
                else       s_xh[row * XHS + pp2(j)] = hh;   // h packed -> cols 0..63
            }
        }
        if (c == 3) {
            #pragma unroll
            for (int cc = 0; cc < 3; ++cc)
                #pragma unroll
                for (int s = 0; s < 2; ++s)
                    #pragma unroll
                    for (int e = 0; e < 4; ++e) {
                        int row = row0 + s * 16 + ((e & 2) ? 8 : 0);
                        int j = cc * 16 + half * 8 + 2 * tig + (e & 1);
                        s_xh[row * XHS + pp2(j)] = hpark[cc * 8 + s * 4 + e];
                    }
        }
        CP_WAIT0;
        __syncthreads();
    }

    // ---- E1(0) prefetch overlapped with h output (packed gather -> coalesced gmem) ----
    stage_async(s_w, g_wp + GW_E1, 5120, t);
    CP_COMMIT;
    {
        float4* hout = (float4*)(out + (size_t)MTOT * 32);
        for (int i = t; i < TOK * 16; i += TPB) {
            int r = i >> 4, c = i & 15;
            int gb = r * XHS + 16 * (c >> 2) + (c & 3);
            float4 v;
            v.x = s_xh[gb]; v.y = s_xh[gb + 4]; v.z = s_xh[gb + 8]; v.w = s_xh[gb + 12];
            hout[(size_t)(base + r) * 16 + c] = v;
        }
    }
    CP_WAIT0;
    __syncthreads();

    // ---- experts: E1 buf0, E2 buf1; A packed both stages ----
    float fq[2][2][4];
    #pragma unroll
    for (int q = 0; q < 2; ++q)
        #pragma unroll
        for (int s = 0; s < 2; ++s)
            { fq[q][s][0] = fq[q][s][1] = fq[q][s][2] = fq[q][s][3] = 0.f; }
    float* eobase = out + (size_t)MTOT * 96;

    #pragma unroll 1
    for (int n = 0; n < 8; ++n) {
        stage_async(s_w + BUF1, g_wp + GW_E2 + n * 2560, 2560, t);
        CP_COMMIT;

        float acc1[4][2][4];
        #pragma unroll
        for (int nt = 0; nt < 4; ++nt) {
            int cb = n * 64 + half * 32 + nt * 8 + 2 * tig;
            float b0 = __ldg(e_b1 + cb), b1 = __ldg(e_b1 + cb + 1);
            #pragma unroll
            for (int s = 0; s < 2; ++s) {
                acc1[nt][s][0] = b0; acc1[nt][s][1] = b1;
                acc1[nt][s][2] = b0; acc1[nt][s][3] = b1;
            }
        }
        #pragma unroll
        for (int kp = 0; kp < 4; ++kp) {
            const int kc = kp * 16 + 4 * tig;
            uint4 bv0 = *(const uint4*)(s_w + (half * 32 + 0 * 8 + gid) * WS + kc);
            uint4 bv1 = *(const uint4*)(s_w + (half * 32 + 1 * 8 + gid) * WS + kc);
            uint4 bv2 = *(const uint4*)(s_w + (half * 32 + 2 * 8 + gid) * WS + kc);
            uint4 bv3 = *(const uint4*)(s_w + (half * 32 + 3 * 8 + gid) * WS + kc);
            LOAD_PA(s_xh + row0 * XHS + kc)                // A = h (packed raw)
            MMA2PE(acc1[0], bv0.x, bv0.y)  MMA2PE(acc1[1], bv1.x, bv1.y)
            MMA2PE(acc1[2], bv2.x, bv2.y)  MMA2PE(acc1[3], bv3.x, bv3.y)
            MMA2PO(acc1[0], bv0.z, bv0.w)  MMA2PO(acc1[1], bv1.z, bv1.w)
            MMA2PO(acc1[2], bv2.z, bv2.w)  MMA2PO(acc1[3], bv3.z, bv3.w)
        }
        #pragma unroll
        for (int nt = 0; nt < 4; ++nt) {   // relu(h1) RNA packed -> cols 64..127
            int c0 = half * 32 + nt * 8 + 2 * tig;
            int q0 = 64 + pp2(c0);
            #pragma unroll
            for (int s = 0; s < 2; ++s) {
                int ra = row0 + s * 16, rb = ra + 8;
                s_xh[ra * XHS + q0]     = f2tf_f(fmaxf(acc1[nt][s][0], 0.f));
                s_xh[ra * XHS + q0 + 4] = f2tf_f(fmaxf(acc1[nt][s][1], 0.f));
                s_xh[rb * XHS + q0]     = f2tf_f(fmaxf(acc1[nt][s][2], 0.f));
                s_xh[rb * XHS + q0 + 4] = f2tf_f(fmaxf(acc1[nt][s][3], 0.f));
            }
        }
        CP_WAIT0;
        __syncthreads();   // h1 visible to pair; E2 weights arrived

        if (n < 7) {
            stage_async(s_w, g_wp + GW_E1 + (n + 1) * 5120, 5120, t);
            CP_COMMIT;
        }
        float acc2[2][2][4];
        #pragma unroll
        for (int nt = 0; nt < 2; ++nt) {
            int cb = n * 32 + half * 16 + nt * 8 + 2 * tig;
            float b0 = __ldg(e_b2 + cb), b1 = __ldg(e_b2 + cb + 1);
            #pragma unroll
            for (int s = 0; s < 2; ++s) {
                acc2[nt][s][0] = b0; acc2[nt][s][1] = b1;
                acc2[nt][s][2] = b0; acc2[nt][s][3] = b1;
            }
        }
        #pragma unroll
        for (int kp = 0; kp < 4; ++kp) {
            const int kc = kp * 16 + 4 * tig;
            uint4 bv0 = *(const uint4*)(s_w + BUF1 + (half * 16 + 0 * 8 + gid) * WS + kc);
            uint4 bv1 = *(const uint4*)(s_w + BUF1 + (half * 16 + 1 * 8 + gid) * WS + kc);
            LOAD_PA(s_xh + row0 * XHS + 64 + kc)           // A = h1 (packed tf32)
            MMA2PE(acc2[0], bv0.x, bv0.y)  MMA2PE(acc2[1], bv1.x, bv1.y)
            MMA2PO(acc2[0], bv0.z, bv0.w)  MMA2PO(acc2[1], bv1.z, bv1.w)
        }
        #pragma unroll
        for (int s = 0; s < 2; ++s) {
            int ra = row0 + s * 16, rb = ra + 8;
            float w0 = s_gate[ra * 8 + n], w1 = s_gate[rb * 8 + n];
            #pragma unroll
            for (int nt = 0; nt < 2; ++nt) {
                fq[nt][s][0] = fmaf(acc2[nt][s][0], w0, fq[nt][s][0]);
                fq[nt][s][1] = fmaf(acc2[nt][s][1], w0, fq[nt][s][1]);
                fq[nt][s][2] = fmaf(acc2[nt][s][2], w1, fq[nt][s][2]);
                fq[nt][s][3] = fmaf(acc2[nt][s][3], w1, fq[nt][s][3]);
                int c0 = n * 32 + half * 16 + nt * 8 + 2 * tig;
                *(float2*)(eobase + (size_t)(base + ra) * 256 + c0) =
                    make_float2(acc2[nt][s][0], acc2[nt][s][1]);
                *(float2*)(eobase + (size_t)(base + rb) * 256 + c0) =
                    make_float2(acc2[nt][s][2], acc2[nt][s][3]);
            }
        }
        CP_WAIT0;
        __syncthreads();
    }

    // ---- final_q ----
    #pragma unroll
    for (int s = 0; s < 2; ++s) {
        int ra = row0 + s * 16, rb = ra + 8;
        #pragma unroll
        for (int nt = 0; nt < 2; ++nt) {
            int c0 = half * 16 + nt * 8 + 2 * tig;
            *(float2*)(out + (size_t)(base + ra) * 32 + c0) =
                make_float2(fq[nt][s][0] * 0.125f, fq[nt][s][1] * 0.125f);
            *(float2*)(out + (size_t)(base + rb) * 32 + c0) =
                make_float2(fq[nt][s][2] * 0.125f, fq[nt][s][3] * 0.125f);
        }
    }
}

extern "C" void kernel_launch(void* const* d_in, const int* in_sizes, int n_in,
                              void* d_out, int out_size) {
    (void)in_sizes; (void)n_in; (void)out_size;
    prep_pack<<<128, 256>>>(
        (const float*)d_in[2],  (const float*)d_in[12],
        (const float*)d_in[4],  (const float*)d_in[5],
        (const float*)d_in[8],  (const float*)d_in[10]);
    cudaFuncSetAttribute(msp_main, cudaFuncAttributeMaxDynamicSharedMemorySize, SMEMF * 4);
    msp_main<<<NBLK, TPB, SMEMF * 4>>>(
        (const float*)d_in[0],  (const float*)d_in[1],
        (const float*)d_in[3],
        (const float*)d_in[6],  (const float*)d_in[7],
        (const float*)d_in[9],  (const float*)d_in[11],
        (const float*)d_in[13],
        (float*)d_out);
}

// round 9
// speedup vs baseline: 1.2772x; 1.2772x over previous
#include <cuda_runtime.h>
#include <math.h>
#include <stdint.h>

#define MTOT 131072
#define TPB  256
#define TOK  128
#define NBLK (MTOT / TOK)

#define XHS 132   // x|h tile row stride (floats)
#define WS  72    // packed K=64 weight row stride
#define FCS 136   // packed K=128 weight row stride

// smem float offsets
#define SW_OFF    0         // ping-pong 2 x 4896
#define SXH_OFF   9792
#define SGATE_OFF 26688
#define SMEMF     27840     // 111,360 B -> 2 CTAs/SM

#define BUF1 4896

// packed-weight global offsets (floats)
#define GW_FC   0
#define GW_GRU  9792
#define GW_E1   37440
#define GW_E2   74304
#define GW_TOT  92736

__device__ __align__(16) float g_wp[GW_TOT];

__device__ __forceinline__ float f2tf_f(float f) {
    uint32_t u; asm("cvt.rna.tf32.f32 %0, %1;" : "=r"(u) : "f"(f));
    return __uint_as_float(u);
}
__device__ __forceinline__ float sig_(float v) { return 1.0f / (1.0f + __expf(-v)); }
__device__ __forceinline__ int packpos(int k) {
    return ((k >> 3) << 3) + ((k & 3) << 1) + ((k >> 2) & 1);
}

__device__ __forceinline__ void cp16(float* dst, const float* src) {
    uint32_t d = (uint32_t)__cvta_generic_to_shared(dst);
    asm volatile("cp.async.cg.shared.global [%0], [%1], 16;" :: "r"(d), "l"(src));
}
__device__ __forceinline__ void stage_async(float* dst, const float* src, int n, int t) {
    for (int i = t * 4; i < n; i += TPB * 4) cp16(dst + i, src + i);
}
#define CP_COMMIT asm volatile("cp.async.commit_group;")
#define CP_WAIT0  asm volatile("cp.async.wait_group 0;")
#define PAIR_BAR  asm volatile("bar.sync %0, 64;" :: "r"(p + 1) : "memory")

__device__ __forceinline__ void mma8(float* d,
    uint32_t a0, uint32_t a1, uint32_t a2, uint32_t a3, uint32_t b0, uint32_t b1)
{
    asm volatile(
        "mma.sync.aligned.m16n8k8.row.col.f32.tf32.tf32.f32 "
        "{%0,%1,%2,%3}, {%4,%5,%6,%7}, {%8,%9}, {%0,%1,%2,%3};"
        : "+f"(d[0]), "+f"(d[1]), "+f"(d[2]), "+f"(d[3])
        : "r"(a0), "r"(a1), "r"(a2), "r"(a3), "r"(b0), "r"(b1));
}

// scalar A-fragments for two m16 stripes into an 8-array
__device__ __forceinline__ void load_a8(uint32_t* A, const float* ptr, int tig) {
    A[0] = __float_as_uint(ptr[tig]);
    A[2] = __float_as_uint(ptr[tig + 4]);
    A[1] = __float_as_uint(ptr[8 * XHS + tig]);
    A[3] = __float_as_uint(ptr[8 * XHS + tig + 4]);
    A[4] = __float_as_uint(ptr[16 * XHS + tig]);
    A[6] = __float_as_uint(ptr[16 * XHS + tig + 4]);
    A[5] = __float_as_uint(ptr[24 * XHS + tig]);
    A[7] = __float_as_uint(ptr[24 * XHS + tig + 4]);
}

#define MMA2A(acc, A, bv)                                       \
    mma8((acc)[0], (A)[0], (A)[1], (A)[2], (A)[3], (bv).x, (bv).y); \
    mma8((acc)[1], (A)[4], (A)[5], (A)[6], (A)[7], (bv).x, (bv).y);

#define COPY_A(dst, src) { _Pragma("unroll") for (int _j = 0; _j < 8; ++_j) (dst)[_j] = (src)[_j]; }

// ---------------- prep: pack + tf32-convert all weights once ----------------
__global__ void prep_pack(const float* __restrict__ fc_w, const float* __restrict__ gate_w,
                          const float* __restrict__ w_ih, const float* __restrict__ w_hh,
                          const float* __restrict__ e_w1, const float* __restrict__ e_w2)
{
    int tid = blockIdx.x * blockDim.x + threadIdx.x;
    int nth = gridDim.x * blockDim.x;
    for (int i = tid; i < 64 * 128; i += nth) {
        int j = i >> 7, k = i & 127;
        g_wp[GW_FC + j * FCS + packpos(k)] = f2tf_f(__ldg(fc_w + i));
    }
    for (int i = tid; i < 8 * 128; i += nth) {
        int j = i >> 7, k = i & 127;
        g_wp[GW_FC + (64 + j) * FCS + packpos(k)] = f2tf_f(__ldg(gate_w + i));
    }
    for (int i = tid; i < 192 * 64; i += nth) {
        int R = i >> 6, k = i & 63;
        int c = (R & 63) >> 4, grp = R >> 6, lr = grp * 16 + (R & 15);
        int d = GW_GRU + c * 6912 + lr * WS + packpos(k);
        g_wp[d]        = f2tf_f(__ldg(w_ih + i));
        g_wp[d + 3456] = f2tf_f(__ldg(w_hh + i));
    }
    for (int i = tid; i < 8 * 64 * 64; i += nth) {
        int n = i >> 12, r = (i >> 6) & 63, k = i & 63;
        g_wp[GW_E1 + n * 4608 + r * WS + packpos(k)] = f2tf_f(__ldg(e_w1 + i));
    }
    for (int i = tid; i < 8 * 32 * 64; i += nth) {
        int n = i >> 11, r = (i >> 6) & 31, k = i & 63;
        g_wp[GW_E2 + n * 2304 + r * WS + packpos(k)] = f2tf_f(__ldg(e_w2 + i));
    }
}

// ---------------- main: 8 warps, paired 32-row stripes, software-pipelined loops ----------------
__global__ void __launch_bounds__(TPB, 2) msp_main(
    const float* __restrict__ xin,  const float* __restrict__ hin,
    const float* __restrict__ fc_b,
    const float* __restrict__ b_ih, const float* __restrict__ b_hh,
    const float* __restrict__ e_b1, const float* __restrict__ e_b2,
    const float* __restrict__ gate_b,
    float* __restrict__ out)
{
    extern __shared__ float sm[];
    float* s_w    = sm + SW_OFF;
    float* s_xh   = sm + SXH_OFF;
    float* s_gate = sm + SGATE_OFF;

    const int t = threadIdx.x, lane = t & 31, wid = t >> 5;
    const int gid = lane >> 2, tig = lane & 3;
    const int p = wid >> 1, half = wid & 1;
    const int r0 = p << 5, base = blockIdx.x * TOK;
    const int row0 = r0 + gid;

    // ---- prologue ----
    stage_async(s_w, g_wp + GW_FC, 9792, t);
    for (int i = t; i < TOK * 16; i += TPB) {
        int r = i >> 4, c = i & 15;
        cp16(s_xh + r * XHS + 64 + c * 4, hin + (size_t)(base + r) * 64 + c * 4);
    }
    CP_COMMIT;
    {
        const float4* xsrc = (const float4*)xin;
        for (int i = t; i < TOK * 16; i += TPB) {
            int r = i >> 4, c = i & 15;
            float4 v = xsrc[(size_t)(base + r) * 32 + c];
            v.x = f2tf_f(v.x); v.y = f2tf_f(v.y); v.z = f2tf_f(v.z); v.w = f2tf_f(v.w);
            *(float4*)(s_xh + r * XHS + c * 4) = v;
        }
    }
    CP_WAIT0;
    __syncthreads();

    // ---- Stage A: x = relu(x_in @ fc_w^T + b); half1 also computes gate ----
    {
        float accF[4][2][4], accG[2][4];
        #pragma unroll
        for (int nt = 0; nt < 4; ++nt) {
            int cb = half * 32 + nt * 8 + 2 * tig;
            float b0 = __ldg(fc_b + cb), b1 = __ldg(fc_b + cb + 1);
            #pragma unroll
            for (int s = 0; s < 2; ++s) {
                accF[nt][s][0] = b0; accF[nt][s][1] = b1;
                accF[nt][s][2] = b0; accF[nt][s][3] = b1;
            }
        }
        {
            float g0 = __ldg(gate_b + 2 * tig), g1 = __ldg(gate_b + 2 * tig + 1);
            #pragma unroll
            for (int s = 0; s < 2; ++s) {
                accG[s][0] = g0; accG[s][1] = g1; accG[s][2] = g0; accG[s][3] = g1;
            }
        }
        #pragma unroll
        for (int kh = 0; kh < 2; ++kh) {
            if (kh == 1) {
                __syncthreads();
                const float4* xsrc = (const float4*)xin;
                for (int i = t; i < TOK * 16; i += TPB) {
                    int r = i >> 4, c = i & 15;
                    float4 v = xsrc[(size_t)(base + r) * 32 + 16 + c];
                    v.x = f2tf_f(v.x); v.y = f2tf_f(v.y); v.z = f2tf_f(v.z); v.w = f2tf_f(v.w);
                    *(float4*)(s_xh + r * XHS + c * 4) = v;
                }
                __syncthreads();
            }
            // prime pipeline for this k-half
            uint32_t Ac[8], An[8];
            uint2 f0, f1, f2, f3, gg, nf0, nf1, nf2, nf3, ngg;
            load_a8(Ac, s_xh + row0 * XHS, tig);
            {
                const int kb = kh * 64 + 2 * tig;
                f0 = *(const uint2*)(s_w + (half * 32 + 0 * 8 + gid) * FCS + kb);
                f1 = *(const uint2*)(s_w + (half * 32 + 1 * 8 + gid) * FCS + kb);
                f2 = *(const uint2*)(s_w + (half * 32 + 2 * 8 + gid) * FCS + kb);
                f3 = *(const uint2*)(s_w + (half * 32 + 3 * 8 + gid) * FCS + kb);
                if (half) gg = *(const uint2*)(s_w + (64 + gid) * FCS + kb);
            }
            #pragma unroll
            for (int ks = 0; ks < 8; ++ks) {
                if (ks < 7) {
                    load_a8(An, s_xh + row0 * XHS + (ks + 1) * 8, tig);
                    const int kb = kh * 64 + (ks + 1) * 8 + 2 * tig;
                    nf0 = *(const uint2*)(s_w + (half * 32 + 0 * 8 + gid) * FCS + kb);
                    nf1 = *(const uint2*)(s_w + (half * 32 + 1 * 8 + gid) * FCS + kb);
                    nf2 = *(const uint2*)(s_w + (half * 32 + 2 * 8 + gid) * FCS + kb);
                    nf3 = *(const uint2*)(s_w + (half * 32 + 3 * 8 + gid) * FCS + kb);
                    if (half) ngg = *(const uint2*)(s_w + (64 + gid) * FCS + kb);
                }
                MMA2A(accF[0], Ac, f0)  MMA2A(accF[1], Ac, f1)
                MMA2A(accF[2], Ac, f2)  MMA2A(accF[3], Ac, f3)
                if (half) MMA2A(accG, Ac, gg)
                if (ks < 7) {
                    COPY_A(Ac, An)
                    f0 = nf0; f1 = nf1; f2 = nf2; f3 = nf3;
                    if (half) gg = ngg;
                }
            }
        }
        PAIR_BAR;   // partner done reading x_in rows of this stripe before overwrite
        #pragma unroll
        for (int nt = 0; nt < 4; ++nt) {
            int c0 = half * 32 + nt * 8 + 2 * tig;
            #pragma unroll
            for (int s = 0; s < 2; ++s) {
                int ra = row0 + s * 16, rb = ra + 8;
                s_xh[ra * XHS + c0]     = f2tf_f(fmaxf(accF[nt][s][0], 0.f));
                s_xh[ra * XHS + c0 + 1] = f2tf_f(fmaxf(accF[nt][s][1], 0.f));
                s_xh[rb * XHS + c0]     = f2tf_f(fmaxf(accF[nt][s][2], 0.f));
                s_xh[rb * XHS + c0 + 1] = f2tf_f(fmaxf(accF[nt][s][3], 0.f));
            }
        }
        if (half) {
            #pragma unroll
            for (int s = 0; s < 2; ++s) {
                int ra = row0 + s * 16, rb = ra + 8;
                s_gate[ra * 9 + 2 * tig]     = sig_(accG[s][0]);
                s_gate[ra * 9 + 2 * tig + 1] = sig_(accG[s][1]);
                s_gate[rb * 9 + 2 * tig]     = sig_(accG[s][2]);
                s_gate[rb * 9 + 2 * tig + 1] = sig_(accG[s][3]);
            }
        }
    }
    __syncthreads();

    // ---- GRU pipeline: 8 stages (ih/hh x 4 chunks) ----
    stage_async(s_w, g_wp + GW_GRU, 3456, t);
    CP_COMMIT;
    CP_WAIT0;
    __syncthreads();

    float hpark[24];
    #pragma unroll 1
    for (int c = 0; c < 4; ++c) {
        stage_async(s_w + BUF1, g_wp + GW_GRU + c * 6912 + 3456, 3456, t);
        CP_COMMIT;

        float ar[2][4], az[2][4], ani[2][4], anh[2][4];
        {
            int j0 = c * 16 + half * 8 + 2 * tig;
            float v0 = __ldg(b_ih + j0) + __ldg(b_hh + j0);
            float v1 = __ldg(b_ih + j0 + 1) + __ldg(b_hh + j0 + 1);
            float z0 = __ldg(b_ih + 64 + j0) + __ldg(b_hh + 64 + j0);
            float z1 = __ldg(b_ih + 64 + j0 + 1) + __ldg(b_hh + 64 + j0 + 1);
            float n0 = __ldg(b_ih + 128 + j0), n1 = __ldg(b_ih + 128 + j0 + 1);
            float m0 = __ldg(b_hh + 128 + j0), m1 = __ldg(b_hh + 128 + j0 + 1);
            #pragma unroll
            for (int s = 0; s < 2; ++s) {
                ar[s][0] = v0; ar[s][1] = v1; ar[s][2] = v0; ar[s][3] = v1;
                az[s][0] = z0; az[s][1] = z1; az[s][2] = z0; az[s][3] = z1;
                ani[s][0] = n0; ani[s][1] = n1; ani[s][2] = n0; ani[s][3] = n1;
                anh[s][0] = m0; anh[s][1] = m1; anh[s][2] = m0; anh[s][3] = m1;
            }
        }
        // x-part (pipelined): A = x (cols 0..63), B = ih chunk in buf0
        {
            uint32_t Ac[8], An[8];
            uint2 br, bz, bn, pr, pz, pn;
            load_a8(Ac, s_xh + row0 * XHS, tig);
            {
                const int kb = 2 * tig;
                br = *(const uint2*)(s_w + (half * 8 + gid) * WS + kb);
                bz = *(const uint2*)(s_w + (16 + half * 8 + gid) * WS + kb);
                bn = *(const uint2*)(s_w + (32 + half * 8 + gid) * WS + kb);
            }
            #pragma unroll
            for (int ks = 0; ks < 8; ++ks) {
                if (ks < 7) {
                    load_a8(An, s_xh + row0 * XHS + (ks + 1) * 8, tig);
                    const int kb = (ks + 1) * 8 + 2 * tig;
                    pr = *(const uint2*)(s_w + (half * 8 + gid) * WS + kb);
                    pz = *(const uint2*)(s_w + (16 + half * 8 + gid) * WS + kb);
                    pn = *(const uint2*)(s_w + (32 + half * 8 + gid) * WS + kb);
                }
                MMA2A(ar, Ac, br)  MMA2A(az, Ac, bz)  MMA2A(ani, Ac, bn)
                if (ks < 7) { COPY_A(Ac, An)  br = pr; bz = pz; bn = pn; }
            }
        }
        CP_WAIT0;
        __syncthreads();

        if (c < 3) stage_async(s_w, g_wp + GW_GRU + (c + 1) * 6912, 3456, t);
        else       stage_async(s_w, g_wp + GW_E1, 4608, t);
        CP_COMMIT;

        // h-part (pipelined): A = h_in (cols 64..127), B = hh chunk in buf1
        {
            uint32_t Ac[8], An[8];
            uint2 br, bz, bn, pr, pz, pn;
            load_a8(Ac, s_xh + row0 * XHS + 64, tig);
            {
                const int kb = 2 * tig;
                br = *(const uint2*)(s_w + BUF1 + (half * 8 + gid) * WS + kb);
                bz = *(const uint2*)(s_w + BUF1 + (16 + half * 8 + gid) * WS + kb);
                bn = *(const uint2*)(s_w + BUF1 + (32 + half * 8 + gid) * WS + kb);
            }
            #pragma unroll
            for (int ks = 0; ks < 8; ++ks) {
                if (ks < 7) {
                    load_a8(An, s_xh + row0 * XHS + 64 + (ks + 1) * 8, tig);
                    const int kb = (ks + 1) * 8 + 2 * tig;
                    pr = *(const uint2*)(s_w + BUF1 + (half * 8 + gid) * WS + kb);
                    pz = *(const uint2*)(s_w + BUF1 + (16 + half * 8 + gid) * WS + kb);
                    pn = *(const uint2*)(s_w + BUF1 + (32 + half * 8 + gid) * WS + kb);
                }
                MMA2A(ar, Ac, br)  MMA2A(az, Ac, bz)  MMA2A(anh, Ac, bn)
                if (ks < 7) { COPY_A(Ac, An)  br = pr; bz = pz; bn = pn; }
            }
        }
        if (c == 3) { PAIR_BAR; }
        #pragma unroll
        for (int s = 0; s < 2; ++s) {
            #pragma unroll
            for (int e = 0; e < 4; ++e) {
                int row = row0 + s * 16 + ((e & 2) ? 8 : 0);
                int j = c * 16 + half * 8 + 2 * tig + (e & 1);
                float rr = sig_(ar[s][e]);
                float zz = sig_(az[s][e]);
                float nn = tanhf(fmaf(rr, anh[s][e], ani[s][e]));
                float hp = s_xh[row * XHS + 64 + j];
                float hh = fmaf(zz, hp - nn, nn);
                if (c < 3) hpark[c * 8 + s * 4 + e] = hh;
                else       s_xh[row * XHS + 64 + j] = hh;
            }
        }
        if (c == 3) {
            #pragma unroll
            for (int cc = 0; cc < 3; ++cc)
                #pragma unroll
                for (int s = 0; s < 2; ++s)
                    #pragma unroll
                    for (int e = 0; e < 4; ++e) {
                        int row = row0 + s * 16 + ((e & 2) ? 8 : 0);
                        int j = cc * 16 + half * 8 + 2 * tig + (e & 1);
                        s_xh[row * XHS + 64 + j] = hpark[cc * 8 + s * 4 + e];
                    }
        }
        CP_WAIT0;
        __syncthreads();
    }

    // ---- h output (coalesced) ----
    {
        float4* hout = (float4*)(out + (size_t)MTOT * 32);
        for (int i = t; i < TOK * 16; i += TPB) {
            int r = i >> 4, c = i & 15;
            hout[(size_t)(base + r) * 16 + c] = *(const float4*)(s_xh + r * XHS + 64 + c * 4);
        }
    }

    // ---- experts: 16 pipelined stages ----
    float fq[2][2][4];
    #pragma unroll
    for (int q = 0; q < 2; ++q)
        #pragma unroll
        for (int s = 0; s < 2; ++s)
            { fq[q][s][0] = fq[q][s][1] = fq[q][s][2] = fq[q][s][3] = 0.f; }
    float* eobase = out + (size_t)MTOT * 96;

    #pragma unroll 1
    for (int n = 0; n < 8; ++n) {
        stage_async(s_w + BUF1, g_wp + GW_E2 + n * 2304, 2304, t);
        CP_COMMIT;

        float acc1[4][2][4];
        #pragma unroll
        for (int nt = 0; nt < 4; ++nt) {
            int cb = n * 64 + half * 32 + nt * 8 + 2 * tig;
            float b0 = __ldg(e_b1 + cb), b1 = __ldg(e_b1 + cb + 1);
            #pragma unroll
            for (int s = 0; s < 2; ++s) {
                acc1[nt][s][0] = b0; acc1[nt][s][1] = b1;
                acc1[nt][s][2] = b0; acc1[nt][s][3] = b1;
            }
        }
        // E1 (pipelined): A = h raw (cols 64..127), B = e_w1[n] in buf0
        {
            uint32_t Ac[8], An[8];
            uint2 c0v, c1v, c2v, c3v, q0v, q1v, q2v, q3v;
            load_a8(Ac, s_xh + row0 * XHS + 64, tig);
            {
                const int kb = 2 * tig;
                c0v = *(const uint2*)(s_w + (half * 32 + 0 * 8 + gid) * WS + kb);
                c1v = *(const uint2*)(s_w + (half * 32 + 1 * 8 + gid) * WS + kb);
                c2v = *(const uint2*)(s_w + (half * 32 + 2 * 8 + gid) * WS + kb);
                c3v = *(const uint2*)(s_w + (half * 32 + 3 * 8 + gid) * WS + kb);
            }
            #pragma unroll
            for (int ks = 0; ks < 8; ++ks) {
                if (ks < 7) {
                    load_a8(An, s_xh + row0 * XHS + 64 + (ks + 1) * 8, tig);
                    const int kb = (ks + 1) * 8 + 2 * tig;
                    q0v = *(const uint2*)(s_w + (half * 32 + 0 * 8 + gid) * WS + kb);
                    q1v = *(const uint2*)(s_w + (half * 32 + 1 * 8 + gid) * WS + kb);
                    q2v = *(const uint2*)(s_w + (half * 32 + 2 * 8 + gid) * WS + kb);
                    q3v = *(const uint2*)(s_w + (half * 32 + 3 * 8 + gid) * WS + kb);
                }
                MMA2A(acc1[0], Ac, c0v)  MMA2A(acc1[1], Ac, c1v)
                MMA2A(acc1[2], Ac, c2v)  MMA2A(acc1[3], Ac, c3v)
                if (ks < 7) { COPY_A(Ac, An)  c0v = q0v; c1v = q1v; c2v = q2v; c3v = q3v; }
            }
        }
        #pragma unroll
        for (int nt = 0; nt < 4; ++nt) {   // relu(h1) RNA -> warp's 32 cols
            int c0 = half * 32 + nt * 8 + 2 * tig;
            #pragma unroll
            for (int s = 0; s < 2; ++s) {
                int ra = row0 + s * 16, rb = ra + 8;
                s_xh[ra * XHS + c0]     = f2tf_f(fmaxf(acc1[nt][s][0], 0.f));
                s_xh[ra * XHS + c0 + 1] = f2tf_f(fmaxf(acc1[nt][s][1], 0.f));
                s_xh[rb * XHS + c0]     = f2tf_f(fmaxf(acc1[nt][s][2], 0.f));
                s_xh[rb * XHS + c0 + 1] = f2tf_f(fmaxf(acc1[nt][s][3], 0.f));
            }
        }
        CP_WAIT0;
        __syncthreads();   // orders h1 writes for partner AND buf1 arrival

        if (n < 7) stage_async(s_w, g_wp + GW_E1 + (n + 1) * 4608, 4608, t);
        CP_COMMIT;

        float acc2[2][2][4];
        #pragma unroll
        for (int nt = 0; nt < 2; ++nt) {
            int cb = n * 32 + half * 16 + nt * 8 + 2 * tig;
            float b0 = __ldg(e_b2 + cb), b1 = __ldg(e_b2 + cb + 1);
            #pragma unroll
            for (int s = 0; s < 2; ++s) {
                acc2[nt][s][0] = b0; acc2[nt][s][1] = b1;
                acc2[nt][s][2] = b0; acc2[nt][s][3] = b1;
            }
        }
        // E2 (pipelined): A = h1 tf32 (cols 0..63), B = e_w2[n] in buf1
        {
            uint32_t Ac[8], An[8];
            uint2 c0v, c1v, q0v, q1v;
            load_a8(Ac, s_xh + row0 * XHS, tig);
            {
                const int kb = 2 * tig;
                c0v = *(const uint2*)(s_w + BUF1 + (half * 16 + 0 * 8 + gid) * WS + kb);
                c1v = *(const uint2*)(s_w + BUF1 + (half * 16 + 1 * 8 + gid) * WS + kb);
            }
            #pragma unroll
            for (int ks = 0; ks < 8; ++ks) {
                if (ks < 7) {
                    load_a8(An, s_xh + row0 * XHS + (ks + 1) * 8, tig);
                    const int kb = (ks + 1) * 8 + 2 * tig;
                    q0v = *(const uint2*)(s_w + BUF1 + (half * 16 + 0 * 8 + gid) * WS + kb);
                    q1v = *(const uint2*)(s_w + BUF1 + (half * 16 + 1 * 8 + gid) * WS + kb);
                }
                MMA2A(acc2[0], Ac, c0v)  MMA2A(acc2[1], Ac, c1v)
                if (ks < 7) { COPY_A(Ac, An)  c0v = q0v; c1v = q1v; }
            }
        }
        #pragma unroll
        for (int s = 0; s < 2; ++s) {
            int ra = row0 + s * 16, rb = ra + 8;
            float w0 = s_gate[ra * 9 + n], w1 = s_gate[rb * 9 + n];
            #pragma unroll
            for (int nt = 0; nt < 2; ++nt) {
                fq[nt][s][0] = fmaf(acc2[nt][s][0], w0, fq[nt][s][0]);
                fq[nt][s][1] = fmaf(acc2[nt][s][1], w0, fq[nt][s][1]);
                fq[nt][s][2] = fmaf(acc2[nt][s][2], w1, fq[nt][s][2]);
                fq[nt][s][3] = fmaf(acc2[nt][s][3], w1, fq[nt][s][3]);
                int c0 = n * 32 + half * 16 + nt * 8 + 2 * tig;
                *(float2*)(eobase + (size_t)(base + ra) * 256 + c0) =
                    make_float2(acc2[nt][s][0], acc2[nt][s][1]);
                *(float2*)(eobase + (size_t)(base + rb) * 256 + c0) =
                    make_float2(acc2[nt][s][2], acc2[nt][s][3]);
            }
        }
        CP_WAIT0;
        __syncthreads();
    }

    // ---- final_q ----
    #pragma unroll
    for (int s = 0; s < 2; ++s) {
        int ra = row0 + s * 16, rb = ra + 8;
        #pragma unroll
        for (int nt = 0; nt < 2; ++nt) {
            int c0 = half * 16 + nt * 8 + 2 * tig;
            *(float2*)(out + (size_t)(base + ra) * 32 + c0) =
                make_float2(fq[nt][s][0] * 0.125f, fq[nt][s][1] * 0.125f);
            *(float2*)(out + (size_t)(base + rb) * 32 + c0) =
                make_float2(fq[nt][s][2] * 0.125f, fq[nt][s][3] * 0.125f);
        }
    }
}

extern "C" void kernel_launch(void* const* d_in, const int* in_sizes, int n_in,
                              void* d_out, int out_size) {
    (void)in_sizes; (void)n_in; (void)out_size;
    prep_pack<<<128, 256>>>(
        (const float*)d_in[2],  (const float*)d_in[12],
        (const float*)d_in[4],  (const float*)d_in[5],
        (const float*)d_in[8],  (const float*)d_in[10]);
    cudaFuncSetAttribute(msp_main, cudaFuncAttributeMaxDynamicSharedMemorySize, SMEMF * 4);
    msp_main<<<NBLK, TPB, SMEMF * 4>>>(
        (const float*)d_in[0],  (const float*)d_in[1],
        (const float*)d_in[3],
        (const float*)d_in[6],  (const float*)d_in[7],
        (const float*)d_in[9],  (const float*)d_in[11],
        (const float*)d_in[13],
        (float*)d_out);
}

// round 10
// speedup vs baseline: 1.3793x; 1.0799x over previous
#include <cuda_runtime.h>
#include <math.h>
#include <stdint.h>

#define MTOT 131072
#define TPB  256
#define TOK  128
#define NBLK (MTOT / TOK)

#define XHS 132   // x|h tile row stride (floats)
#define WS  72    // packed K=64 weight row stride
#define FCS 136   // packed K=128 weight row stride

// smem float offsets
#define SW_OFF    0         // ping-pong 2 x 4896
#define SXH_OFF   9792
#define SGATE_OFF 26688
#define SMEMF     27840     // 111,360 B -> 2 CTAs/SM

#define BUF1 4896

// packed-weight global offsets (floats)
#define GW_FC   0
#define GW_GRU  9792
#define GW_E1   37440
#define GW_E2   74304
#define GW_TOT  92736

__device__ __align__(16) float g_wp[GW_TOT];

__device__ __forceinline__ float f2tf_f(float f) {
    uint32_t u; asm("cvt.rna.tf32.f32 %0, %1;" : "=r"(u) : "f"(f));
    return __uint_as_float(u);
}
// single-MUFU hardware tanh (sm_75+); rel err <= 2^-11
__device__ __forceinline__ float tanh_f(float v) {
    float y; asm("tanh.approx.f32 %0, %1;" : "=f"(y) : "f"(v)); return y;
}
// sigmoid(x) = 0.5*tanh(x/2) + 0.5  -> 1 MUFU + 2 FMA (no div, no ex2 chain)
__device__ __forceinline__ float sig_(float v) {
    return fmaf(tanh_f(0.5f * v), 0.5f, 0.5f);
}
__device__ __forceinline__ int packpos(int k) {
    return ((k >> 3) << 3) + ((k & 3) << 1) + ((k >> 2) & 1);
}

__device__ __forceinline__ void cp16(float* dst, const float* src) {
    uint32_t d = (uint32_t)__cvta_generic_to_shared(dst);
    asm volatile("cp.async.cg.shared.global [%0], [%1], 16;" :: "r"(d), "l"(src));
}
__device__ __forceinline__ void stage_async(float* dst, const float* src, int n, int t) {
    for (int i = t * 4; i < n; i += TPB * 4) cp16(dst + i, src + i);
}
#define CP_COMMIT asm volatile("cp.async.commit_group;")
#define CP_WAIT0  asm volatile("cp.async.wait_group 0;")
#define PAIR_BAR  asm volatile("bar.sync %0, 64;" :: "r"(p + 1) : "memory")

__device__ __forceinline__ void mma8(float* d,
    uint32_t a0, uint32_t a1, uint32_t a2, uint32_t a3, uint32_t b0, uint32_t b1)
{
    asm volatile(
        "mma.sync.aligned.m16n8k8.row.col.f32.tf32.tf32.f32 "
        "{%0,%1,%2,%3}, {%4,%5,%6,%7}, {%8,%9}, {%0,%1,%2,%3};"
        : "+f"(d[0]), "+f"(d[1]), "+f"(d[2]), "+f"(d[3])
        : "r"(a0), "r"(a1), "r"(a2), "r"(a3), "r"(b0), "r"(b1));
}

// scalar A-fragments for two m16 stripes into an 8-array
__device__ __forceinline__ void load_a8(uint32_t* A, const float* ptr, int tig) {
    A[0] = __float_as_uint(ptr[tig]);
    A[2] = __float_as_uint(ptr[tig + 4]);
    A[1] = __float_as_uint(ptr[8 * XHS + tig]);
    A[3] = __float_as_uint(ptr[8 * XHS + tig + 4]);
    A[4] = __float_as_uint(ptr[16 * XHS + tig]);
    A[6] = __float_as_uint(ptr[16 * XHS + tig + 4]);
    A[5] = __float_as_uint(ptr[24 * XHS + tig]);
    A[7] = __float_as_uint(ptr[24 * XHS + tig + 4]);
}

#define MMA2A(acc, A, bv)                                       \
    mma8((acc)[0], (A)[0], (A)[1], (A)[2], (A)[3], (bv).x, (bv).y); \
    mma8((acc)[1], (A)[4], (A)[5], (A)[6], (A)[7], (bv).x, (bv).y);

#define COPY_A(dst, src) { _Pragma("unroll") for (int _j = 0; _j < 8; ++_j) (dst)[_j] = (src)[_j]; }

// ---------------- prep: pack + tf32-convert all weights once ----------------
__global__ void prep_pack(const float* __restrict__ fc_w, const float* __restrict__ gate_w,
                          const float* __restrict__ w_ih, const float* __restrict__ w_hh,
                          const float* __restrict__ e_w1, const float* __restrict__ e_w2)
{
    int tid = blockIdx.x * blockDim.x + threadIdx.x;
    int nth = gridDim.x * blockDim.x;
    for (int i = tid; i < 64 * 128; i += nth) {
        int j = i >> 7, k = i & 127;
        g_wp[GW_FC + j * FCS + packpos(k)] = f2tf_f(__ldg(fc_w + i));
    }
    for (int i = tid; i < 8 * 128; i += nth) {
        int j = i >> 7, k = i & 127;
        g_wp[GW_FC + (64 + j) * FCS + packpos(k)] = f2tf_f(__ldg(gate_w + i));
    }
    for (int i = tid; i < 192 * 64; i += nth) {
        int R = i >> 6, k = i & 63;
        int c = (R & 63) >> 4, grp = R >> 6, lr = grp * 16 + (R & 15);
        int d = GW_GRU + c * 6912 + lr * WS + packpos(k);
        g_wp[d]        = f2tf_f(__ldg(w_ih + i));
        g_wp[d + 3456] = f2tf_f(__ldg(w_hh + i));
    }
    for (int i = tid; i < 8 * 64 * 64; i += nth) {
        int n = i >> 12, r = (i >> 6) & 63, k = i & 63;
        g_wp[GW_E1 + n * 4608 + r * WS + packpos(k)] = f2tf_f(__ldg(e_w1 + i));
    }
    for (int i = tid; i < 8 * 32 * 64; i += nth) {
        int n = i >> 11, r = (i >> 6) & 31, k = i & 63;
        g_wp[GW_E2 + n * 2304 + r * WS + packpos(k)] = f2tf_f(__ldg(e_w2 + i));
    }
}

// ---------------- main: 8 warps, paired 32-row stripes, software-pipelined loops ----------------
__global__ void __launch_bounds__(TPB, 2) msp_main(
    const float* __restrict__ xin,  const float* __restrict__ hin,
    const float* __restrict__ fc_b,
    const float* __restrict__ b_ih, const float* __restrict__ b_hh,
    const float* __restrict__ e_b1, const float* __restrict__ e_b2,
    const float* __restrict__ gate_b,
    float* __restrict__ out)
{
    extern __shared__ float sm[];
    float* s_w    = sm + SW_OFF;
    float* s_xh   = sm + SXH_OFF;
    float* s_gate = sm + SGATE_OFF;

    const int t = threadIdx.x, lane = t & 31, wid = t >> 5;
    const int gid = lane >> 2, tig = lane & 3;
    const int p = wid >> 1, half = wid & 1;
    const int r0 = p << 5, base = blockIdx.x * TOK;
    const int row0 = r0 + gid;

    // ---- prologue ----
    stage_async(s_w, g_wp + GW_FC, 9792, t);
    for (int i = t; i < TOK * 16; i += TPB) {
        int r = i >> 4, c = i & 15;
        cp16(s_xh + r * XHS + 64 + c * 4, hin + (size_t)(base + r) * 64 + c * 4);
    }
    CP_COMMIT;
    {
        const float4* xsrc = (const float4*)xin;
        for (int i = t; i < TOK * 16; i += TPB) {
            int r = i >> 4, c = i & 15;
            float4 v = xsrc[(size_t)(base + r) * 32 + c];
            v.x = f2tf_f(v.x); v.y = f2tf_f(v.y); v.z = f2tf_f(v.z); v.w = f2tf_f(v.w);
            *(float4*)(s_xh + r * XHS + c * 4) = v;
        }
    }
    CP_WAIT0;
    __syncthreads();

    // ---- Stage A: x = relu(x_in @ fc_w^T + b); half1 also computes gate ----
    {
        float accF[4][2][4], accG[2][4];
        #pragma unroll
        for (int nt = 0; nt < 4; ++nt) {
            int cb = half * 32 + nt * 8 + 2 * tig;
            float b0 = __ldg(fc_b + cb), b1 = __ldg(fc_b + cb + 1);
            #pragma unroll
            for (int s = 0; s < 2; ++s) {
                accF[nt][s][0] = b0; accF[nt][s][1] = b1;
                accF[nt][s][2] = b0; accF[nt][s][3] = b1;
            }
        }
        {
            float g0 = __ldg(gate_b + 2 * tig), g1 = __ldg(gate_b + 2 * tig + 1);
            #pragma unroll
            for (int s = 0; s < 2; ++s) {
                accG[s][0] = g0; accG[s][1] = g1; accG[s][2] = g0; accG[s][3] = g1;
            }
        }
        #pragma unroll
        for (int kh = 0; kh < 2; ++kh) {
            if (kh == 1) {
                __syncthreads();
                const float4* xsrc = (const float4*)xin;
                for (int i = t; i < TOK * 16; i += TPB) {
                    int r = i >> 4, c = i & 15;
                    float4 v = xsrc[(size_t)(base + r) * 32 + 16 + c];
                    v.x = f2tf_f(v.x); v.y = f2tf_f(v.y); v.z = f2tf_f(v.z); v.w = f2tf_f(v.w);
                    *(float4*)(s_xh + r * XHS + c * 4) = v;
                }
                __syncthreads();
            }
            // prime pipeline for this k-half
            uint32_t Ac[8], An[8];
            uint2 f0, f1, f2, f3, gg, nf0, nf1, nf2, nf3, ngg;
            load_a8(Ac, s_xh + row0 * XHS, tig);
            {
                const int kb = kh * 64 + 2 * tig;
                f0 = *(const uint2*)(s_w + (half * 32 + 0 * 8 + gid) * FCS + kb);
                f1 = *(const uint2*)(s_w + (half * 32 + 1 * 8 + gid) * FCS + kb);
                f2 = *(const uint2*)(s_w + (half * 32 + 2 * 8 + gid) * FCS + kb);
                f3 = *(const uint2*)(s_w + (half * 32 + 3 * 8 + gid) * FCS + kb);
                if (half) gg = *(const uint2*)(s_w + (64 + gid) * FCS + kb);
            }
            #pragma unroll
            for (int ks = 0; ks < 8; ++ks) {
                if (ks < 7) {
                    load_a8(An, s_xh + row0 * XHS + (ks + 1) * 8, tig);
                    const int kb = kh * 64 + (ks + 1) * 8 + 2 * tig;
                    nf0 = *(const uint2*)(s_w + (half * 32 + 0 * 8 + gid) * FCS + kb);
                    nf1 = *(const uint2*)(s_w + (half * 32 + 1 * 8 + gid) * FCS + kb);
                    nf2 = *(const uint2*)(s_w + (half * 32 + 2 * 8 + gid) * FCS + kb);
                    nf3 = *(const uint2*)(s_w + (half * 32 + 3 * 8 + gid) * FCS + kb);
                    if (half) ngg = *(const uint2*)(s_w + (64 + gid) * FCS + kb);
                }
                MMA2A(accF[0], Ac, f0)  MMA2A(accF[1], Ac, f1)
                MMA2A(accF[2], Ac, f2)  MMA2A(accF[3], Ac, f3)
                if (half) MMA2A(accG, Ac, gg)
                if (ks < 7) {
                    COPY_A(Ac, An)
                    f0 = nf0; f1 = nf1; f2 = nf2; f3 = nf3;
                    if (half) gg = ngg;
                }
            }
        }
        PAIR_BAR;   // partner done reading x_in rows of this stripe before overwrite
        #pragma unroll
        for (int nt = 0; nt < 4; ++nt) {
            int c0 = half * 32 + nt * 8 + 2 * tig;
            #pragma unroll
            for (int s = 0; s < 2; ++s) {
                int ra = row0 + s * 16, rb = ra + 8;
                s_xh[ra * XHS + c0]     = f2tf_f(fmaxf(accF[nt][s][0], 0.f));
                s_xh[ra * XHS + c0 + 1] = f2tf_f(fmaxf(accF[nt][s][1], 0.f));
                s_xh[rb * XHS + c0]     = f2tf_f(fmaxf(accF[nt][s][2], 0.f));
                s_xh[rb * XHS + c0 + 1] = f2tf_f(fmaxf(accF[nt][s][3], 0.f));
            }
        }
        if (half) {
            #pragma unroll
            for (int s = 0; s < 2; ++s) {
                int ra = row0 + s * 16, rb = ra + 8;
                s_gate[ra * 9 + 2 * tig]     = sig_(accG[s][0]);
                s_gate[ra * 9 + 2 * tig + 1] = sig_(accG[s][1]);
                s_gate[rb * 9 + 2 * tig]     = sig_(accG[s][2]);
                s_gate[rb * 9 + 2 * tig + 1] = sig_(accG[s][3]);
            }
        }
    }
    __syncthreads();

    // ---- GRU pipeline: 8 stages (ih/hh x 4 chunks) ----
    stage_async(s_w, g_wp + GW_GRU, 3456, t);
    CP_COMMIT;
    CP_WAIT0;
    __syncthreads();

    float hpark[24];
    #pragma unroll 1
    for (int c = 0; c < 4; ++c) {
        stage_async(s_w + BUF1, g_wp + GW_GRU + c * 6912 + 3456, 3456, t);
        CP_COMMIT;

        float ar[2][4], az[2][4], ani[2][4], anh[2][4];
        {
            int j0 = c * 16 + half * 8 + 2 * tig;
            float v0 = __ldg(b_ih + j0) + __ldg(b_hh + j0);
            float v1 = __ldg(b_ih + j0 + 1) + __ldg(b_hh + j0 + 1);
            float z0 = __ldg(b_ih + 64 + j0) + __ldg(b_hh + 64 + j0);
            float z1 = __ldg(b_ih + 64 + j0 + 1) + __ldg(b_hh + 64 + j0 + 1);
            float n0 = __ldg(b_ih + 128 + j0), n1 = __ldg(b_ih + 128 + j0 + 1);
            float m0 = __ldg(b_hh + 128 + j0), m1 = __ldg(b_hh + 128 + j0 + 1);
            #pragma unroll
            for (int s = 0; s < 2; ++s) {
                ar[s][0] = v0; ar[s][1] = v1; ar[s][2] = v0; ar[s][3] = v1;
                az[s][0] = z0; az[s][1] = z1; az[s][2] = z0; az[s][3] = z1;
                ani[s][0] = n0; ani[s][1] = n1; ani[s][2] = n0; ani[s][3] = n1;
                anh[s][0] = m0; anh[s][1] = m1; anh[s][2] = m0; anh[s][3] = m1;
            }
        }
        // x-part (pipelined): A = x (cols 0..63), B = ih chunk in buf0
        {
            uint32_t Ac[8], An[8];
            uint2 br, bz, bn, pr, pz, pn;
            load_a8(Ac, s_xh + row0 * XHS, tig);
            {
                const int kb = 2 * tig;
                br = *(const uint2*)(s_w + (half * 8 + gid) * WS + kb);
                bz = *(const uint2*)(s_w + (16 + half * 8 + gid) * WS + kb);
                bn = *(const uint2*)(s_w + (32 + half * 8 + gid) * WS + kb);
            }
            #pragma unroll
            for (int ks = 0; ks < 8; ++ks) {
                if (ks < 7) {
                    load_a8(An, s_xh + row0 * XHS + (ks + 1) * 8, tig);
                    const int kb = (ks + 1) * 8 + 2 * tig;
                    pr = *(const uint2*)(s_w + (half * 8 + gid) * WS + kb);
                    pz = *(const uint2*)(s_w + (16 + half * 8 + gid) * WS + kb);
                    pn = *(const uint2*)(s_w + (32 + half * 8 + gid) * WS + kb);
                }
                MMA2A(ar, Ac, br)  MMA2A(az, Ac, bz)  MMA2A(ani, Ac, bn)
                if (ks < 7) { COPY_A(Ac, An)  br = pr; bz = pz; bn = pn; }
            }
        }
        CP_WAIT0;
        __syncthreads();

        if (c < 3) stage_async(s_w, g_wp + GW_GRU + (c + 1) * 6912, 3456, t);
        else       stage_async(s_w, g_wp + GW_E1, 4608, t);
        CP_COMMIT;

        // h-part (pipelined): A = h_in (cols 64..127), B = hh chunk in buf1
        {
            uint32_t Ac[8], An[8];
            uint2 br, bz, bn, pr, pz, pn;
            load_a8(Ac, s_xh + row0 * XHS + 64, tig);
            {
                const int kb = 2 * tig;
                br = *(const uint2*)(s_w + BUF1 + (half * 8 + gid) * WS + kb);
                bz = *(const uint2*)(s_w + BUF1 + (16 + half * 8 + gid) * WS + kb);
                bn = *(const uint2*)(s_w + BUF1 + (32 + half * 8 + gid) * WS + kb);
            }
            #pragma unroll
            for (int ks = 0; ks < 8; ++ks) {
                if (ks < 7) {
                    load_a8(An, s_xh + row0 * XHS + 64 + (ks + 1) * 8, tig);
                    const int kb = (ks + 1) * 8 + 2 * tig;
                    pr = *(const uint2*)(s_w + BUF1 + (half * 8 + gid) * WS + kb);
                    pz = *(const uint2*)(s_w + BUF1 + (16 + half * 8 + gid) * WS + kb);
                    pn = *(const uint2*)(s_w + BUF1 + (32 + half * 8 + gid) * WS + kb);
                }
                MMA2A(ar, Ac, br)  MMA2A(az, Ac, bz)  MMA2A(anh, Ac, bn)
                if (ks < 7) { COPY_A(Ac, An)  br = pr; bz = pz; bn = pn; }
            }
        }
        if (c == 3) { PAIR_BAR; }
        #pragma unroll
        for (int s = 0; s < 2; ++s) {
            #pragma unroll
            for (int e = 0; e < 4; ++e) {
                int row = row0 + s * 16 + ((e & 2) ? 8 : 0);
                int j = c * 16 + half * 8 + 2 * tig + (e & 1);
                float rr = sig_(ar[s][e]);
                float zz = sig_(az[s][e]);
                float nn = tanh_f(fmaf(rr, anh[s][e], ani[s][e]));
                float hp = s_xh[row * XHS + 64 + j];
                float hh = fmaf(zz, hp - nn, nn);
                if (c < 3) hpark[c * 8 + s * 4 + e] = hh;
                else       s_xh[row * XHS + 64 + j] = hh;
            }
        }
        if (c == 3) {
            #pragma unroll
            for (int cc = 0; cc < 3; ++cc)
                #pragma unroll
                for (int s = 0; s < 2; ++s)
                    #pragma unroll
                    for (int e = 0; e < 4; ++e) {
                        int row = row0 + s * 16 + ((e & 2) ? 8 : 0);
                        int j = cc * 16 + half * 8 + 2 * tig + (e & 1);
                        s_xh[row * XHS + 64 + j] = hpark[cc * 8 + s * 4 + e];
                    }
        }
        CP_WAIT0;
        __syncthreads();
    }

    // ---- h output (coalesced) ----
    {
        float4* hout = (float4*)(out + (size_t)MTOT * 32);
        for (int i = t; i < TOK * 16; i += TPB) {
            int r = i >> 4, c = i & 15;
            hout[(size_t)(base + r) * 16 + c] = *(const float4*)(s_xh + r * XHS + 64 + c * 4);
        }
    }

    // ---- experts: 16 pipelined stages ----
    float fq[2][2][4];
    #pragma unroll
    for (int q = 0; q < 2; ++q)
        #pragma unroll
        for (int s = 0; s < 2; ++s)
            { fq[q][s][0] = fq[q][s][1] = fq[q][s][2] = fq[q][s][3] = 0.f; }
    float* eobase = out + (size_t)MTOT * 96;

    #pragma unroll 1
    for (int n = 0; n < 8; ++n) {
        stage_async(s_w + BUF1, g_wp + GW_E2 + n * 2304, 2304, t);
        CP_COMMIT;

        float acc1[4][2][4];
        #pragma unroll
        for (int nt = 0; nt < 4; ++nt) {
            int cb = n * 64 + half * 32 + nt * 8 + 2 * tig;
            float b0 = __ldg(e_b1 + cb), b1 = __ldg(e_b1 + cb + 1);
            #pragma unroll
            for (int s = 0; s < 2; ++s) {
                acc1[nt][s][0] = b0; acc1[nt][s][1] = b1;
                acc1[nt][s][2] = b0; acc1[nt][s][3] = b1;
            }
        }
        // E1 (pipelined): A = h raw (cols 64..127), B = e_w1[n] in buf0
        {
            uint32_t Ac[8], An[8];
            uint2 c0v, c1v, c2v, c3v, q0v, q1v, q2v, q3v;
            load_a8(Ac, s_xh + row0 * XHS + 64, tig);
            {
                const int kb = 2 * tig;
                c0v = *(const uint2*)(s_w + (half * 32 + 0 * 8 + gid) * WS + kb);
                c1v = *(const uint2*)(s_w + (half * 32 + 1 * 8 + gid) * WS + kb);
                c2v = *(const uint2*)(s_w + (half * 32 + 2 * 8 + gid) * WS + kb);
                c3v = *(const uint2*)(s_w + (half * 32 + 3 * 8 + gid) * WS + kb);
            }
            #pragma unroll
            for (int ks = 0; ks < 8; ++ks) {
                if (ks < 7) {
                    load_a8(An, s_xh + row0 * XHS + 64 + (ks + 1) * 8, tig);
                    const int kb = (ks + 1) * 8 + 2 * tig;
                    q0v = *(const uint2*)(s_w + (half * 32 + 0 * 8 + gid) * WS + kb);
                    q1v = *(const uint2*)(s_w + (half * 32 + 1 * 8 + gid) * WS + kb);
                    q2v = *(const uint2*)(s_w + (half * 32 + 2 * 8 + gid) * WS + kb);
                    q3v = *(const uint2*)(s_w + (half * 32 + 3 * 8 + gid) * WS + kb);
                }
                MMA2A(acc1[0], Ac, c0v)  MMA2A(acc1[1], Ac, c1v)
                MMA2A(acc1[2], Ac, c2v)  MMA2A(acc1[3], Ac, c3v)
                if (ks < 7) { COPY_A(Ac, An)  c0v = q0v; c1v = q1v; c2v = q2v; c3v = q3v; }
            }
        }
        #pragma unroll
        for (int nt = 0; nt < 4; ++nt) {   // relu(h1) RNA -> warp's 32 cols
            int c0 = half * 32 + nt * 8 + 2 * tig;
            #pragma unroll
            for (int s = 0; s < 2; ++s) {
                int ra = row0 + s * 16, rb = ra + 8;
                s_xh[ra * XHS + c0]     = f2tf_f(fmaxf(acc1[nt][s][0], 0.f));
                s_xh[ra * XHS + c0 + 1] = f2tf_f(fmaxf(acc1[nt][s][1], 0.f));
                s_xh[rb * XHS + c0]     = f2tf_f(fmaxf(acc1[nt][s][2], 0.f));
                s_xh[rb * XHS + c0 + 1] = f2tf_f(fmaxf(acc1[nt][s][3], 0.f));
            }
        }
        CP_WAIT0;
        __syncthreads();   // orders h1 writes for partner AND buf1 arrival

        if (n < 7) stage_async(s_w, g_wp + GW_E1 + (n + 1) * 4608, 4608, t);
        CP_COMMIT;

        float acc2[2][2][4];
        #pragma unroll
        for (int nt = 0; nt < 2; ++nt) {
            int cb = n * 32 + half * 16 + nt * 8 + 2 * tig;
            float b0 = __ldg(e_b2 + cb), b1 = __ldg(e_b2 + cb + 1);
            #pragma unroll
            for (int s = 0; s < 2; ++s) {
                acc2[nt][s][0] = b0; acc2[nt][s][1] = b1;
                acc2[nt][s][2] = b0; acc2[nt][s][3] = b1;
            }
        }
        // E2 (pipelined): A = h1 tf32 (cols 0..63), B = e_w2[n] in buf1
        {
            uint32_t Ac[8], An[8];
            uint2 c0v, c1v, q0v, q1v;
            load_a8(Ac, s_xh + row0 * XHS, tig);
            {
                const int kb = 2 * tig;
                c0v = *(const uint2*)(s_w + BUF1 + (half * 16 + 0 * 8 + gid) * WS + kb);
                c1v = *(const uint2*)(s_w + BUF1 + (half * 16 + 1 * 8 + gid) * WS + kb);
            }
            #pragma unroll
            for (int ks = 0; ks < 8; ++ks) {
                if (ks < 7) {
                    load_a8(An, s_xh + row0 * XHS + (ks + 1) * 8, tig);
                    const int kb = (ks + 1) * 8 + 2 * tig;
                    q0v = *(const uint2*)(s_w + BUF1 + (half * 16 + 0 * 8 + gid) * WS + kb);
                    q1v = *(const uint2*)(s_w + BUF1 + (half * 16 + 1 * 8 + gid) * WS + kb);
                }
                MMA2A(acc2[0], Ac, c0v)  MMA2A(acc2[1], Ac, c1v)
                if (ks < 7) { COPY_A(Ac, An)  c0v = q0v; c1v = q1v; }
            }
        }
        #pragma unroll
        for (int s = 0; s < 2; ++s) {
            int ra = row0 + s * 16, rb = ra + 8;
            float w0 = s_gate[ra * 9 + n], w1 = s_gate[rb * 9 + n];
            #pragma unroll
            for (int nt = 0; nt < 2; ++nt) {
                fq[nt][s][0] = fmaf(acc2[nt][s][0], w0, fq[nt][s][0]);
                fq[nt][s][1] = fmaf(acc2[nt][s][1], w0, fq[nt][s][1]);
                fq[nt][s][2] = fmaf(acc2[nt][s][2], w1, fq[nt][s][2]);
                fq[nt][s][3] = fmaf(acc2[nt][s][3], w1, fq[nt][s][3]);
                int c0 = n * 32 + half * 16 + nt * 8 + 2 * tig;
                *(float2*)(eobase + (size_t)(base + ra) * 256 + c0) =
                    make_float2(acc2[nt][s][0], acc2[nt][s][1]);
                *(float2*)(eobase + (size_t)(base + rb) * 256 + c0) =
                    make_float2(acc2[nt][s][2], acc2[nt][s][3]);
            }
        }
        CP_WAIT0;
        __syncthreads();
    }

    // ---- final_q ----
    #pragma unroll
    for (int s = 0; s < 2; ++s) {
        int ra = row0 + s * 16, rb = ra + 8;
        #pragma unroll
        for (int nt = 0; nt < 2; ++nt) {
            int c0 = half * 16 + nt * 8 + 2 * tig;
            *(float2*)(out + (size_t)(base + ra) * 32 + c0) =
                make_float2(fq[nt][s][0] * 0.125f, fq[nt][s][1] * 0.125f);
            *(float2*)(out + (size_t)(base + rb) * 32 + c0) =
                make_float2(fq[nt][s][2] * 0.125f, fq[nt][s][3] * 0.125f);
        }
    }
}

extern "C" void kernel_launch(void* const* d_in, const int* in_sizes, int n_in,
                              void* d_out, int out_size) {
    (void)in_sizes; (void)n_in; (void)out_size;
    prep_pack<<<128, 256>>>(
        (const float*)d_in[2],  (const float*)d_in[12],
        (const float*)d_in[4],  (const float*)d_in[5],
        (const float*)d_in[8],  (const float*)d_in[10]);
    cudaFuncSetAttribute(msp_main, cudaFuncAttributeMaxDynamicSharedMemorySize, SMEMF * 4);
    msp_main<<<NBLK, TPB, SMEMF * 4>>>(
        (const float*)d_in[0],  (const float*)d_in[1],
        (const float*)d_in[3],
        (const float*)d_in[6],  (const float*)d_in[7],
        (const float*)d_in[9],  (const float*)d_in[11],
        (const float*)d_in[13],
        (float*)d_out);
}

// round 11
// speedup vs baseline: 1.8620x; 1.3500x over previous
#include <cuda_runtime.h>
#include <cuda_fp16.h>
#include <math.h>
#include <stdint.h>

#define MTOT 131072
#define TPB  256
#define TOK  128
#define NBLK (MTOT / TOK)

// word (uint32/half2) strides
#define XHS 68    // x|h tile row stride in words; %32==4 -> conflict-free scalar A loads
#define WS  40    // K=64 weight row stride in words (32 data + 8 pad); %32==8 -> LDS.64 ok
#define FCS 72    // K=128 weight row stride in words (64 data + 8 pad); %32==8

// smem word offsets
#define SW_OFF    0        // buf0 = +0 (5184), buf1 = +5184 (2560)
#define BUF1      5184
#define SXH_OFF   7744
#define SGATE_OFF 16448    // [128][9] f32
#define SMEMW     17600    // 70,400 B -> 2 CTAs/SM easily

// packed-weight global offsets (words)
#define GW_FC   0          // [72][72] fc(64 rows)+gate(8 rows), K=128
#define GW_GRU  5184       // 4 chunks x (ih [48][40] + hh [48][40]) = 15360
#define GW_E1   20544      // [8][64][40] = 20480
#define GW_E2   41024      // [8][32][40] = 10240
#define GW_TOT  51264

__device__ __align__(16) uint32_t g_wp[GW_TOT];

__device__ __forceinline__ uint32_t h2u(float a, float b) {
    __half2 h = __floats2half2_rn(a, b);
    return *reinterpret_cast<uint32_t*>(&h);
}
__device__ __forceinline__ float2 u2f2(uint32_t u) {
    __half2 h = *reinterpret_cast<__half2*>(&u);
    return __half22float2(h);
}
__device__ __forceinline__ float tanh_f(float v) {
    float y; asm("tanh.approx.f32 %0, %1;" : "=f"(y) : "f"(v)); return y;
}
__device__ __forceinline__ float sig_(float v) {
    return fmaf(tanh_f(0.5f * v), 0.5f, 0.5f);
}
// word-pair packing: (w, w+4) adjacent within 8-word groups
__device__ __forceinline__ int wp_(int w) {
    return ((w >> 3) << 3) + ((w & 3) << 1) + ((w >> 2) & 1);
}

__device__ __forceinline__ void cp16w(uint32_t* dst, const uint32_t* src) {
    uint32_t d = (uint32_t)__cvta_generic_to_shared(dst);
    asm volatile("cp.async.cg.shared.global [%0], [%1], 16;" :: "r"(d), "l"(src));
}
__device__ __forceinline__ void stage_async(uint32_t* dst, const uint32_t* src, int n, int t) {
    for (int i = t * 4; i < n; i += TPB * 4) cp16w(dst + i, src + i);
}
#define CP_COMMIT asm volatile("cp.async.commit_group;")
#define CP_WAIT0  asm volatile("cp.async.wait_group 0;")
#define PAIR_BAR  asm volatile("bar.sync %0, 64;" :: "r"(p + 1) : "memory")

// fp16 m16n8k16, fp32 accumulate
__device__ __forceinline__ void mma16(float* d,
    uint32_t a0, uint32_t a1, uint32_t a2, uint32_t a3, uint32_t b0, uint32_t b1)
{
    asm volatile(
        "mma.sync.aligned.m16n8k16.row.col.f32.f16.f16.f32 "
        "{%0,%1,%2,%3}, {%4,%5,%6,%7}, {%8,%9}, {%0,%1,%2,%3};"
        : "+f"(d[0]), "+f"(d[1]), "+f"(d[2]), "+f"(d[3])
        : "r"(a0), "r"(a1), "r"(a2), "r"(a3), "r"(b0), "r"(b1));
}

// A-fragments (words) for two m16 stripes
#define LOAD_A8(ptr)                              \
    uint32_t a0 = (ptr)[tig];                     \
    uint32_t a2 = (ptr)[tig + 4];                 \
    uint32_t a1 = (ptr)[8 * XHS + tig];           \
    uint32_t a3 = (ptr)[8 * XHS + tig + 4];       \
    uint32_t a4 = (ptr)[16 * XHS + tig];          \
    uint32_t a6 = (ptr)[16 * XHS + tig + 4];      \
    uint32_t a5 = (ptr)[24 * XHS + tig];          \
    uint32_t a7 = (ptr)[24 * XHS + tig + 4];

#define MMA2(acc, bv)                                       \
    mma16((acc)[0], a0, a1, a2, a3, (bv).x, (bv).y);        \
    mma16((acc)[1], a4, a5, a6, a7, (bv).x, (bv).y);

// ---------------- prep: pack + fp16-convert all weights once ----------------
__global__ void prep_pack(const float* __restrict__ fc_w, const float* __restrict__ gate_w,
                          const float* __restrict__ w_ih, const float* __restrict__ w_hh,
                          const float* __restrict__ e_w1, const float* __restrict__ e_w2)
{
    int tid = blockIdx.x * blockDim.x + threadIdx.x;
    int nth = gridDim.x * blockDim.x;
    for (int i = tid; i < 72 * 64; i += nth) {        // FC + gate, K=128 (64 words)
        int j = i >> 6, w = i & 63;
        const float* src = (j < 64) ? (fc_w + j * 128) : (gate_w + (j - 64) * 128);
        g_wp[GW_FC + j * FCS + wp_(w)] = h2u(src[2 * w], src[2 * w + 1]);
    }
    for (int i = tid; i < 192 * 32; i += nth) {       // GRU, K=64 (32 words)
        int R = i >> 5, w = i & 31;
        int c = (R & 63) >> 4, grp = R >> 6, lr = grp * 16 + (R & 15);
        int d = GW_GRU + c * 3840 + lr * WS + wp_(w);
        g_wp[d]        = h2u(w_ih[R * 64 + 2 * w], w_ih[R * 64 + 2 * w + 1]);
        g_wp[d + 1920] = h2u(w_hh[R * 64 + 2 * w], w_hh[R * 64 + 2 * w + 1]);
    }
    for (int i = tid; i < 8 * 64 * 32; i += nth) {    // E1
        int n = i >> 11, r = (i >> 5) & 63, w = i & 31;
        const float* src = e_w1 + n * 4096 + r * 64;
        g_wp[GW_E1 + n * 2560 + r * WS + wp_(w)] = h2u(src[2 * w], src[2 * w + 1]);
    }
    for (int i = tid; i < 8 * 32 * 32; i += nth) {    // E2
        int n = i >> 10, r = (i >> 5) & 31, w = i & 31;
        const float* src = e_w2 + n * 2048 + r * 64;
        g_wp[GW_E2 + n * 1280 + r * WS + wp_(w)] = h2u(src[2 * w], src[2 * w + 1]);
    }
}

// ---------------- main: 8 warps, paired 32-row stripes, fp16 k16 mmas ----------------
__global__ void __launch_bounds__(TPB, 2) msp_main(
    const float* __restrict__ xin,  const float* __restrict__ hin,
    const float* __restrict__ fc_b,
    const float* __restrict__ b_ih, const float* __restrict__ b_hh,
    const float* __restrict__ e_b1, const float* __restrict__ e_b2,
    const float* __restrict__ gate_b,
    float* __restrict__ out)
{
    extern __shared__ uint32_t smw[];
    uint32_t* s_w  = smw + SW_OFF;
    uint32_t* s_xh = smw + SXH_OFF;   // per row: words 0..31 = x_in-half/x/h1, 32..63 = h_in/h
    float* s_gate  = (float*)(smw + SGATE_OFF);

    const int t = threadIdx.x, lane = t & 31, wid = t >> 5;
    const int gid = lane >> 2, tig = lane & 3;
    const int p = wid >> 1, half = wid & 1;
    const int r0 = p << 5, base = blockIdx.x * TOK;
    const int row0 = r0 + gid;

    // ---- prologue: FC -> buf0, GRU-ih0 -> buf1, h_in + x_in half0 (fp16) ----
    stage_async(s_w, g_wp + GW_FC, 5184, t);
    stage_async(s_w + BUF1, g_wp + GW_GRU, 1920, t);
    CP_COMMIT;
    {
        const float4* hsrc = (const float4*)hin;
        for (int i = t; i < TOK * 16; i += TPB) {
            int r = i >> 4, c = i & 15;
            float4 v = hsrc[(size_t)(base + r) * 16 + c];
            *(uint2*)(s_xh + r * XHS + 32 + 2 * c) =
                make_uint2(h2u(v.x, v.y), h2u(v.z, v.w));
        }
        const float4* xsrc = (const float4*)xin;
        for (int i = t; i < TOK * 16; i += TPB) {
            int r = i >> 4, c = i & 15;
            float4 v = xsrc[(size_t)(base + r) * 32 + c];
            *(uint2*)(s_xh + r * XHS + 2 * c) =
                make_uint2(h2u(v.x, v.y), h2u(v.z, v.w));
        }
    }
    CP_WAIT0;
    __syncthreads();

    // ---- Stage A: x = relu(x_in @ fc_w^T + b); half1 warps also compute gate ----
    {
        float accF[4][2][4], accG[2][4];
        #pragma unroll
        for (int nt = 0; nt < 4; ++nt) {
            int cb = half * 32 + nt * 8 + 2 * tig;
            float b0 = __ldg(fc_b + cb), b1 = __ldg(fc_b + cb + 1);
            #pragma unroll
            for (int s = 0; s < 2; ++s) {
                accF[nt][s][0] = b0; accF[nt][s][1] = b1;
                accF[nt][s][2] = b0; accF[nt][s][3] = b1;
            }
        }
        {
            float g0 = __ldg(gate_b + 2 * tig), g1 = __ldg(gate_b + 2 * tig + 1);
            #pragma unroll
            for (int s = 0; s < 2; ++s) {
                accG[s][0] = g0; accG[s][1] = g1; accG[s][2] = g0; accG[s][3] = g1;
            }
        }
        #pragma unroll
        for (int kh = 0; kh < 2; ++kh) {
            if (kh == 1) {
                __syncthreads();
                const float4* xsrc = (const float4*)xin;
                for (int i = t; i < TOK * 16; i += TPB) {
                    int r = i >> 4, c = i & 15;
                    float4 v = xsrc[(size_t)(base + r) * 32 + 16 + c];
                    *(uint2*)(s_xh + r * XHS + 2 * c) =
                        make_uint2(h2u(v.x, v.y), h2u(v.z, v.w));
                }
                __syncthreads();
            }
            #pragma unroll
            for (int ks = 0; ks < 4; ++ks) {
                const uint32_t* ap = s_xh + row0 * XHS + ks * 8;
                LOAD_A8(ap)
                const int kb = (kh * 4 + ks) * 8 + 2 * tig;
                #pragma unroll
                for (int nt = 0; nt < 4; ++nt) {
                    uint2 bv = *(const uint2*)(s_w + (half * 32 + nt * 8 + gid) * FCS + kb);
                    MMA2(accF[nt], bv)
                }
                if (half) {
                    uint2 gv = *(const uint2*)(s_w + (64 + gid) * FCS + kb);
                    MMA2(accG, gv)
                }
            }
        }
        PAIR_BAR;   // partner done reading x_in before packed overwrite
        #pragma unroll
        for (int nt = 0; nt < 4; ++nt) {
            int wq = half * 16 + nt * 4 + tig;   // word of cols (c0, c0+1)
            #pragma unroll
            for (int s = 0; s < 2; ++s) {
                int ra = row0 + s * 16, rb = ra + 8;
                s_xh[ra * XHS + wq] = h2u(fmaxf(accF[nt][s][0], 0.f), fmaxf(accF[nt][s][1], 0.f));
                s_xh[rb * XHS + wq] = h2u(fmaxf(accF[nt][s][2], 0.f), fmaxf(accF[nt][s][3], 0.f));
            }
        }
        if (half) {
            #pragma unroll
            for (int s = 0; s < 2; ++s) {
                int ra = row0 + s * 16, rb = ra + 8;
                s_gate[ra * 9 + 2 * tig]     = sig_(accG[s][0]);
                s_gate[ra * 9 + 2 * tig + 1] = sig_(accG[s][1]);
                s_gate[rb * 9 + 2 * tig]     = sig_(accG[s][2]);
                s_gate[rb * 9 + 2 * tig + 1] = sig_(accG[s][3]);
            }
        }
    }
    __syncthreads();   // stage-A buf0 reads done

    // ---- GRU: 4 chunks; ih in buf1 (prefetched), hh staged into buf0 ----
    float hpark[24];
    #pragma unroll 1
    for (int c = 0; c < 4; ++c) {
        stage_async(s_w, g_wp + GW_GRU + c * 3840 + 1920, 1920, t);   // hh(c) -> buf0
        CP_COMMIT;

        float ar[2][4], az[2][4], ani[2][4], anh[2][4];
        {
            int j0 = c * 16 + half * 8 + 2 * tig;
            float v0 = __ldg(b_ih + j0) + __ldg(b_hh + j0);
            float v1 = __ldg(b_ih + j0 + 1) + __ldg(b_hh + j0 + 1);
            float z0 = __ldg(b_ih + 64 + j0) + __ldg(b_hh + 64 + j0);
            float z1 = __ldg(b_ih + 64 + j0 + 1) + __ldg(b_hh + 64 + j0 + 1);
            float n0 = __ldg(b_ih + 128 + j0), n1 = __ldg(b_ih + 128 + j0 + 1);
            float m0 = __ldg(b_hh + 128 + j0), m1 = __ldg(b_hh + 128 + j0 + 1);
            #pragma unroll
            for (int s = 0; s < 2; ++s) {
                ar[s][0] = v0; ar[s][1] = v1; ar[s][2] = v0; ar[s][3] = v1;
                az[s][0] = z0; az[s][1] = z1; az[s][2] = z0; az[s][3] = z1;
                ani[s][0] = n0; ani[s][1] = n1; ani[s][2] = n0; ani[s][3] = n1;
                anh[s][0] = m0; anh[s][1] = m1; anh[s][2] = m0; anh[s][3] = m1;
            }
        }
        // x-part: A = x (words 0..31), B = ih(c) in buf1
        #pragma unroll
        for (int ks = 0; ks < 4; ++ks) {
            const uint32_t* ap = s_xh + row0 * XHS + ks * 8;
            LOAD_A8(ap)
            const int kb = ks * 8 + 2 * tig;
            uint2 br = *(const uint2*)(s_w + BUF1 + (half * 8 + gid) * WS + kb);
            MMA2(ar, br)
            uint2 bz = *(const uint2*)(s_w + BUF1 + (16 + half * 8 + gid) * WS + kb);
            MMA2(az, bz)
            uint2 bn = *(const uint2*)(s_w + BUF1 + (32 + half * 8 + gid) * WS + kb);
            MMA2(ani, bn)
        }
        CP_WAIT0;
        __syncthreads();   // hh(c) arrived; buf1 reads done

        if (c < 3) stage_async(s_w + BUF1, g_wp + GW_GRU + (c + 1) * 3840, 1920, t);
        else       stage_async(s_w + BUF1, g_wp + GW_E1, 2560, t);    // E1(0)
        CP_COMMIT;

        // h-part: A = h_in (words 32..63), B = hh(c) in buf0
        #pragma unroll
        for (int ks = 0; ks < 4; ++ks) {
            const uint32_t* ap = s_xh + row0 * XHS + 32 + ks * 8;
            LOAD_A8(ap)
            const int kb = ks * 8 + 2 * tig;
            uint2 br = *(const uint2*)(s_w + (half * 8 + gid) * WS + kb);
            MMA2(ar, br)
            uint2 bz = *(const uint2*)(s_w + (16 + half * 8 + gid) * WS + kb);
            MMA2(az, bz)
            uint2 bn = *(const uint2*)(s_w + (32 + half * 8 + gid) * WS + kb);
            MMA2(anh, bn)
        }
        if (c == 3) { PAIR_BAR; }  // partner finished h_in reads before h writes
        #pragma unroll
        for (int s = 0; s < 2; ++s) {
            #pragma unroll
            for (int rb_ = 0; rb_ < 2; ++rb_) {
                int row = row0 + s * 16 + rb_ * 8;
                int j = c * 16 + half * 8 + 2 * tig;
                int e0 = rb_ * 2;
                float2 hp = u2f2(s_xh[row * XHS + 32 + (j >> 1)]);
                float r0_ = sig_(ar[s][e0]),     r1_ = sig_(ar[s][e0 + 1]);
                float z0_ = sig_(az[s][e0]),     z1_ = sig_(az[s][e0 + 1]);
                float n0_ = tanh_f(fmaf(r0_, anh[s][e0],     ani[s][e0]));
                float n1_ = tanh_f(fmaf(r1_, anh[s][e0 + 1], ani[s][e0 + 1]));
                float h0_ = fmaf(z0_, hp.x - n0_, n0_);
                float h1_ = fmaf(z1_, hp.y - n1_, n1_);
                if (c < 3) { hpark[c * 8 + s * 4 + e0] = h0_; hpark[c * 8 + s * 4 + e0 + 1] = h1_; }
                else s_xh[row * XHS + 32 + (j >> 1)] = h2u(h0_, h1_);
            }
        }
        if (c == 3) {
            #pragma unroll
            for (int cc = 0; cc < 3; ++cc)
                #pragma unroll
                for (int s = 0; s < 2; ++s)
                    #pragma unroll
                    for (int rb_ = 0; rb_ < 2; ++rb_) {
                        int row = row0 + s * 16 + rb_ * 8;
                        int j = cc * 16 + half * 8 + 2 * tig;
                        s_xh[row * XHS + 32 + (j >> 1)] =
                            h2u(hpark[cc * 8 + s * 4 + rb_ * 2],
                                hpark[cc * 8 + s * 4 + rb_ * 2 + 1]);
                    }
        }
        CP_WAIT0;
        __syncthreads();
    }

    // ---- h output (fp16 smem -> f32 gmem, coalesced) ----
    {
        float4* hout = (float4*)(out + (size_t)MTOT * 32);
        for (int i = t; i < TOK * 16; i += TPB) {
            int r = i >> 4, c = i & 15;
            uint2 w2 = *(const uint2*)(s_xh + r * XHS + 32 + 2 * c);
            float2 f0 = u2f2(w2.x), f1 = u2f2(w2.y);
            hout[(size_t)(base + r) * 16 + c] = make_float4(f0.x, f0.y, f1.x, f1.y);
        }
    }

    // ---- experts: E1 in buf1, E2 staged into buf0 ----
    float fq[2][2][4];
    #pragma unroll
    for (int q = 0; q < 2; ++q)
        #pragma unroll
        for (int s = 0; s < 2; ++s)
            { fq[q][s][0] = fq[q][s][1] = fq[q][s][2] = fq[q][s][3] = 0.f; }
    float* eobase = out + (size_t)MTOT * 96;

    #pragma unroll 1
    for (int n = 0; n < 8; ++n) {
        stage_async(s_w, g_wp + GW_E2 + n * 1280, 1280, t);   // E2(n) -> buf0
        CP_COMMIT;

        float acc1[4][2][4];
        #pragma unroll
        for (int nt = 0; nt < 4; ++nt) {
            int cb = n * 64 + half * 32 + nt * 8 + 2 * tig;
            float b0 = __ldg(e_b1 + cb), b1 = __ldg(e_b1 + cb + 1);
            #pragma unroll
            for (int s = 0; s < 2; ++s) {
                acc1[nt][s][0] = b0; acc1[nt][s][1] = b1;
                acc1[nt][s][2] = b0; acc1[nt][s][3] = b1;
            }
        }
        // E1: A = h (words 32..63), B = e_w1[n] in buf1
        #pragma unroll
        for (int ks = 0; ks < 4; ++ks) {
            const uint32_t* ap = s_xh + row0 * XHS + 32 + ks * 8;
            LOAD_A8(ap)
            const int kb = ks * 8 + 2 * tig;
            #pragma unroll
            for (int nt = 0; nt < 4; ++nt) {
                uint2 bv = *(const uint2*)(s_w + BUF1 + (half * 32 + nt * 8 + gid) * WS + kb);
                MMA2(acc1[nt], bv)
            }
        }
        #pragma unroll
        for (int nt = 0; nt < 4; ++nt) {   // relu(h1) fp16 -> words 0..31
            int wq = half * 16 + nt * 4 + tig;
            #pragma unroll
            for (int s = 0; s < 2; ++s) {
                int ra = row0 + s * 16, rb = ra + 8;
                s_xh[ra * XHS + wq] = h2u(fmaxf(acc1[nt][s][0], 0.f), fmaxf(acc1[nt][s][1], 0.f));
                s_xh[rb * XHS + wq] = h2u(fmaxf(acc1[nt][s][2], 0.f), fmaxf(acc1[nt][s][3], 0.f));
            }
        }
        CP_WAIT0;
        __syncthreads();   // h1 visible to pair; E2 weights arrived

        if (n < 7) stage_async(s_w + BUF1, g_wp + GW_E1 + (n + 1) * 2560, 2560, t);
        CP_COMMIT;

        float acc2[2][2][4];
        #pragma unroll
        for (int nt = 0; nt < 2; ++nt) {
            int cb = n * 32 + half * 16 + nt * 8 + 2 * tig;
            float b0 = __ldg(e_b2 + cb), b1 = __ldg(e_b2 + cb + 1);
            #pragma unroll
            for (int s = 0; s < 2; ++s) {
                acc2[nt][s][0] = b0; acc2[nt][s][1] = b1;
                acc2[nt][s][2] = b0; acc2[nt][s][3] = b1;
            }
        }
        // E2: A = h1 (words 0..31), B = e_w2[n] in buf0
        #pragma unroll
        for (int ks = 0; ks < 4; ++ks) {
            const uint32_t* ap = s_xh + row0 * XHS + ks * 8;
            LOAD_A8(ap)
            const int kb = ks * 8 + 2 * tig;
            #pragma unroll
            for (int nt = 0; nt < 2; ++nt) {
                uint2 bv = *(const uint2*)(s_w + (half * 16 + nt * 8 + gid) * WS + kb);
                MMA2(acc2[nt], bv)
            }
        }
        #pragma unroll
        for (int s = 0; s < 2; ++s) {
            int ra = row0 + s * 16, rb = ra + 8;
            float w0 = s_gate[ra * 9 + n], w1 = s_gate[rb * 9 + n];
            #pragma unroll
            for (int nt = 0; nt < 2; ++nt) {
                fq[nt][s][0] = fmaf(acc2[nt][s][0], w0, fq[nt][s][0]);
                fq[nt][s][1] = fmaf(acc2[nt][s][1], w0, fq[nt][s][1]);
                fq[nt][s][2] = fmaf(acc2[nt][s][2], w1, fq[nt][s][2]);
                fq[nt][s][3] = fmaf(acc2[nt][s][3], w1, fq[nt][s][3]);
                int c0 = n * 32 + half * 16 + nt * 8 + 2 * tig;
                *(float2*)(eobase + (size_t)(base + ra) * 256 + c0) =
                    make_float2(acc2[nt][s][0], acc2[nt][s][1]);
                *(float2*)(eobase + (size_t)(base + rb) * 256 + c0) =
                    make_float2(acc2[nt][s][2], acc2[nt][s][3]);
            }
        }
        CP_WAIT0;
        __syncthreads();
    }

    // ---- final_q ----
    #pragma unroll
    for (int s = 0; s < 2; ++s) {
        int ra = row0 + s * 16, rb = ra + 8;
        #pragma unroll
        for (int nt = 0; nt < 2; ++nt) {
            int c0 = half * 16 + nt * 8 + 2 * tig;
            *(float2*)(out + (size_t)(base + ra) * 32 + c0) =
                make_float2(fq[nt][s][0] * 0.125f, fq[nt][s][1] * 0.125f);
            *(float2*)(out + (size_t)(base + rb) * 32 + c0) =
                make_float2(fq[nt][s][2] * 0.125f, fq[nt][s][3] * 0.125f);
        }
    }
}

extern "C" void kernel_launch(void* const* d_in, const int* in_sizes, int n_in,
                              void* d_out, int out_size) {
    (void)in_sizes; (void)n_in; (void)out_size;
    prep_pack<<<128, 256>>>(
        (const float*)d_in[2],  (const float*)d_in[12],
        (const float*)d_in[4],  (const float*)d_in[5],
        (const float*)d_in[8],  (const float*)d_in[10]);
    cudaFuncSetAttribute(msp_main, cudaFuncAttributeMaxDynamicSharedMemorySize, SMEMW * 4);
    msp_main<<<NBLK, TPB, SMEMW * 4>>>(
        (const float*)d_in[0],  (const float*)d_in[1],
        (const float*)d_in[3],
        (const float*)d_in[6],  (const float*)d_in[7],
        (const float*)d_in[9],  (const float*)d_in[11],
        (const float*)d_in[13],
        (float*)d_out);
}

// round 12
// speedup vs baseline: 1.9047x; 1.0230x over previous
#include <cuda_runtime.h>
#include <cuda_fp16.h>
#include <math.h>
#include <stdint.h>

#define MTOT 131072
#define TPB  256
#define TOK  128
#define NBLK (MTOT / TOK)

// word (uint32/half2) strides
#define XHS 68    // x|h tile row stride in words; %32==4 -> conflict-free scalar A loads
#define WS  40    // K=64 weight row stride in words; %32==8 -> LDS.64 conflict-free
#define FCS 72    // K=128 weight row stride in words

// smem word offsets
#define SW_OFF    0        // two 5184-word buffers
#define BUF1      5184
#define SXH_OFF   10368
#define SGATE_OFF 19072    // [128][9] f32
#define SMEMW     20224    // 80,896 B -> 2 CTAs/SM (161.8 KB)

// packed-weight global offsets (words)
#define GW_FC   0          // [72][72] fc(64)+gate(8), K=128
#define GW_GRU  5184       // 4 chunks x 3840 (ih [48][40] @ +0, hh @ +1920)
#define GW_E    20544      // 8 experts x 3840 (E1 [64][40] @ +0, E2 [32][40] @ +2560)
#define GW_TOT  51264

__device__ __align__(16) uint32_t g_wp[GW_TOT];

__device__ __forceinline__ uint32_t h2u(float a, float b) {
    __half2 h = __floats2half2_rn(a, b);
    return *reinterpret_cast<uint32_t*>(&h);
}
__device__ __forceinline__ float2 u2f2(uint32_t u) {
    __half2 h = *reinterpret_cast<__half2*>(&u);
    return __half22float2(h);
}
__device__ __forceinline__ float tanh_f(float v) {
    float y; asm("tanh.approx.f32 %0, %1;" : "=f"(y) : "f"(v)); return y;
}
__device__ __forceinline__ float sig_(float v) {
    return fmaf(tanh_f(0.5f * v), 0.5f, 0.5f);
}
// word-pair packing: (w, w+4) adjacent within 8-word groups
__device__ __forceinline__ int wp_(int w) {
    return ((w >> 3) << 3) + ((w & 3) << 1) + ((w >> 2) & 1);
}

__device__ __forceinline__ void cp16w(uint32_t* dst, const uint32_t* src) {
    uint32_t d = (uint32_t)__cvta_generic_to_shared(dst);
    asm volatile("cp.async.cg.shared.global [%0], [%1], 16;" :: "r"(d), "l"(src));
}
__device__ __forceinline__ void stage_async(uint32_t* dst, const uint32_t* src, int n, int t) {
    for (int i = t * 4; i < n; i += TPB * 4) cp16w(dst + i, src + i);
}
#define CP_COMMIT asm volatile("cp.async.commit_group;")
#define CP_WAIT0  asm volatile("cp.async.wait_group 0;")
#define PAIR_BAR  asm volatile("bar.sync %0, 64;" :: "r"(p + 1) : "memory")

// fp16 m16n8k16, fp32 accumulate
__device__ __forceinline__ void mma16(float* d,
    uint32_t a0, uint32_t a1, uint32_t a2, uint32_t a3, uint32_t b0, uint32_t b1)
{
    asm volatile(
        "mma.sync.aligned.m16n8k16.row.col.f32.f16.f16.f32 "
        "{%0,%1,%2,%3}, {%4,%5,%6,%7}, {%8,%9}, {%0,%1,%2,%3};"
        : "+f"(d[0]), "+f"(d[1]), "+f"(d[2]), "+f"(d[3])
        : "r"(a0), "r"(a1), "r"(a2), "r"(a3), "r"(b0), "r"(b1));
}

#define LOAD_A8(ptr)                              \
    uint32_t a0 = (ptr)[tig];                     \
    uint32_t a2 = (ptr)[tig + 4];                 \
    uint32_t a1 = (ptr)[8 * XHS + tig];           \
    uint32_t a3 = (ptr)[8 * XHS + tig + 4];       \
    uint32_t a4 = (ptr)[16 * XHS + tig];          \
    uint32_t a6 = (ptr)[16 * XHS + tig + 4];      \
    uint32_t a5 = (ptr)[24 * XHS + tig];          \
    uint32_t a7 = (ptr)[24 * XHS + tig + 4];

#define MMA2(acc, bv)                                       \
    mma16((acc)[0], a0, a1, a2, a3, (bv).x, (bv).y);        \
    mma16((acc)[1], a4, a5, a6, a7, (bv).x, (bv).y);

// ---------------- prep: pack + fp16-convert all weights once ----------------
__global__ void prep_pack(const float* __restrict__ fc_w, const float* __restrict__ gate_w,
                          const float* __restrict__ w_ih, const float* __restrict__ w_hh,
                          const float* __restrict__ e_w1, const float* __restrict__ e_w2)
{
    int tid = blockIdx.x * blockDim.x + threadIdx.x;
    int nth = gridDim.x * blockDim.x;
    for (int i = tid; i < 72 * 64; i += nth) {        // FC + gate, K=128 (64 words)
        int j = i >> 6, w = i & 63;
        const float* src = (j < 64) ? (fc_w + j * 128) : (gate_w + (j - 64) * 128);
        g_wp[GW_FC + j * FCS + wp_(w)] = h2u(src[2 * w], src[2 * w + 1]);
    }
    for (int i = tid; i < 192 * 32; i += nth) {       // GRU chunks
        int R = i >> 5, w = i & 31;
        int c = (R & 63) >> 4, grp = R >> 6, lr = grp * 16 + (R & 15);
        int d = GW_GRU + c * 3840 + lr * WS + wp_(w);
        g_wp[d]        = h2u(w_ih[R * 64 + 2 * w], w_ih[R * 64 + 2 * w + 1]);
        g_wp[d + 1920] = h2u(w_hh[R * 64 + 2 * w], w_hh[R * 64 + 2 * w + 1]);
    }
    for (int i = tid; i < 8 * 64 * 32; i += nth) {    // E1 (expert-merged block)
        int n = i >> 11, r = (i >> 5) & 63, w = i & 31;
        const float* src = e_w1 + n * 4096 + r * 64;
        g_wp[GW_E + n * 3840 + r * WS + wp_(w)] = h2u(src[2 * w], src[2 * w + 1]);
    }
    for (int i = tid; i < 8 * 32 * 32; i += nth) {    // E2
        int n = i >> 10, r = (i >> 5) & 31, w = i & 31;
        const float* src = e_w2 + n * 2048 + r * 64;
        g_wp[GW_E + n * 3840 + 2560 + r * WS + wp_(w)] = h2u(src[2 * w], src[2 * w + 1]);
    }
}

// ---------------- main: 8 warps, paired 32-row stripes, merged staging ----------------
__global__ void __launch_bounds__(TPB, 2) msp_main(
    const float* __restrict__ xin,  const float* __restrict__ hin,
    const float* __restrict__ fc_b,
    const float* __restrict__ b_ih, const float* __restrict__ b_hh,
    const float* __restrict__ e_b1, const float* __restrict__ e_b2,
    const float* __restrict__ gate_b,
    float* __restrict__ out)
{
    extern __shared__ uint32_t smw[];
    uint32_t* s_w  = smw + SW_OFF;
    uint32_t* s_xh = smw + SXH_OFF;   // per row: words 0..31 = x-half/x/h1, 32..63 = h_in/h
    float* s_gate  = (float*)(smw + SGATE_OFF);

    const int t = threadIdx.x, lane = t & 31, wid = t >> 5;
    const int gid = lane >> 2, tig = lane & 3;
    const int p = wid >> 1, half = wid & 1;
    const int r0 = p << 5, base = blockIdx.x * TOK;
    const int row0 = r0 + gid;

    // ---- prologue: FC -> buf0, GRU(0) -> buf1, h_in + x_in half0 (fp16) ----
    stage_async(s_w, g_wp + GW_FC, 5184, t);
    stage_async(s_w + BUF1, g_wp + GW_GRU, 3840, t);
    CP_COMMIT;
    {
        const float4* hsrc = (const float4*)hin;
        for (int i = t; i < TOK * 16; i += TPB) {
            int r = i >> 4, c = i & 15;
            float4 v = hsrc[(size_t)(base + r) * 16 + c];
            *(uint2*)(s_xh + r * XHS + 32 + 2 * c) =
                make_uint2(h2u(v.x, v.y), h2u(v.z, v.w));
        }
        const float4* xsrc = (const float4*)xin;
        for (int i = t; i < TOK * 16; i += TPB) {
            int r = i >> 4, c = i & 15;
            float4 v = xsrc[(size_t)(base + r) * 32 + c];
            *(uint2*)(s_xh + r * XHS + 2 * c) =
                make_uint2(h2u(v.x, v.y), h2u(v.z, v.w));
        }
    }
    CP_WAIT0;
    __syncthreads();

    // ---- Stage A: x = relu(x_in @ fc_w^T + b); half1 warps also compute gate ----
    {
        float accF[4][2][4], accG[2][4];
        #pragma unroll
        for (int nt = 0; nt < 4; ++nt) {
            int cb = half * 32 + nt * 8 + 2 * tig;
            float b0 = __ldg(fc_b + cb), b1 = __ldg(fc_b + cb + 1);
            #pragma unroll
            for (int s = 0; s < 2; ++s) {
                accF[nt][s][0] = b0; accF[nt][s][1] = b1;
                accF[nt][s][2] = b0; accF[nt][s][3] = b1;
            }
        }
        {
            float g0 = __ldg(gate_b + 2 * tig), g1 = __ldg(gate_b + 2 * tig + 1);
            #pragma unroll
            for (int s = 0; s < 2; ++s) {
                accG[s][0] = g0; accG[s][1] = g1; accG[s][2] = g0; accG[s][3] = g1;
            }
        }
        #pragma unroll
        for (int kh = 0; kh < 2; ++kh) {
            if (kh == 1) {
                __syncthreads();
                const float4* xsrc = (const float4*)xin;
                for (int i = t; i < TOK * 16; i += TPB) {
                    int r = i >> 4, c = i & 15;
                    float4 v = xsrc[(size_t)(base + r) * 32 + 16 + c];
                    *(uint2*)(s_xh + r * XHS + 2 * c) =
                        make_uint2(h2u(v.x, v.y), h2u(v.z, v.w));
                }
                __syncthreads();
            }
            #pragma unroll
            for (int ks = 0; ks < 4; ++ks) {
                const uint32_t* ap = s_xh + row0 * XHS + ks * 8;
                LOAD_A8(ap)
                const int kb = (kh * 4 + ks) * 8 + 2 * tig;
                #pragma unroll
                for (int nt = 0; nt < 4; ++nt) {
                    uint2 bv = *(const uint2*)(s_w + (half * 32 + nt * 8 + gid) * FCS + kb);
                    MMA2(accF[nt], bv)
                }
                if (half) {
                    uint2 gv = *(const uint2*)(s_w + (64 + gid) * FCS + kb);
                    MMA2(accG, gv)
                }
            }
        }
        PAIR_BAR;   // partner done reading x_in before overwrite
        #pragma unroll
        for (int nt = 0; nt < 4; ++nt) {
            int wq = half * 16 + nt * 4 + tig;
            #pragma unroll
            for (int s = 0; s < 2; ++s) {
                int ra = row0 + s * 16, rb = ra + 8;
                s_xh[ra * XHS + wq] = h2u(fmaxf(accF[nt][s][0], 0.f), fmaxf(accF[nt][s][1], 0.f));
                s_xh[rb * XHS + wq] = h2u(fmaxf(accF[nt][s][2], 0.f), fmaxf(accF[nt][s][3], 0.f));
            }
        }
        if (half) {
            #pragma unroll
            for (int s = 0; s < 2; ++s) {
                int ra = row0 + s * 16, rb = ra + 8;
                s_gate[ra * 9 + 2 * tig]     = sig_(accG[s][0]);
                s_gate[ra * 9 + 2 * tig + 1] = sig_(accG[s][1]);
                s_gate[rb * 9 + 2 * tig]     = sig_(accG[s][2]);
                s_gate[rb * 9 + 2 * tig + 1] = sig_(accG[s][3]);
            }
        }
    }
    __syncthreads();   // stage-A buf0 reads done

    // ---- GRU: 4 chunks, ONE sync per chunk (ih+hh staged together) ----
    float hpark[24];
    #pragma unroll 1
    for (int c = 0; c < 4; ++c) {
        uint32_t* cur = (c & 1) ? s_w : s_w + BUF1;   // c0 in buf1 (prologue)
        uint32_t* oth = (c & 1) ? s_w + BUF1 : s_w;
        if (c < 3) stage_async(oth, g_wp + GW_GRU + (c + 1) * 3840, 3840, t);
        else       stage_async(oth, g_wp + GW_E, 3840, t);          // E(0) -> buf1
        CP_COMMIT;

        float ar[2][4], az[2][4], ani[2][4], anh[2][4];
        {
            int j0 = c * 16 + half * 8 + 2 * tig;
            float v0 = __ldg(b_ih + j0) + __ldg(b_hh + j0);
            float v1 = __ldg(b_ih + j0 + 1) + __ldg(b_hh + j0 + 1);
            float z0 = __ldg(b_ih + 64 + j0) + __ldg(b_hh + 64 + j0);
            float z1 = __ldg(b_ih + 64 + j0 + 1) + __ldg(b_hh + 64 + j0 + 1);
            float n0 = __ldg(b_ih + 128 + j0), n1 = __ldg(b_ih + 128 + j0 + 1);
            float m0 = __ldg(b_hh + 128 + j0), m1 = __ldg(b_hh + 128 + j0 + 1);
            #pragma unroll
            for (int s = 0; s < 2; ++s) {
                ar[s][0] = v0; ar[s][1] = v1; ar[s][2] = v0; ar[s][3] = v1;
                az[s][0] = z0; az[s][1] = z1; az[s][2] = z0; az[s][3] = z1;
                ani[s][0] = n0; ani[s][1] = n1; ani[s][2] = n0; ani[s][3] = n1;
                anh[s][0] = m0; anh[s][1] = m1; anh[s][2] = m0; anh[s][3] = m1;
            }
        }
        // x-part: A = x (words 0..31), B = ih @ cur
        #pragma unroll
        for (int ks = 0; ks < 4; ++ks) {
            const uint32_t* ap = s_xh + row0 * XHS + ks * 8;
            LOAD_A8(ap)
            const int kb = ks * 8 + 2 * tig;
            uint2 br = *(const uint2*)(cur + (half * 8 + gid) * WS + kb);
            MMA2(ar, br)
            uint2 bz = *(const uint2*)(cur + (16 + half * 8 + gid) * WS + kb);
            MMA2(az, bz)
            uint2 bn = *(const uint2*)(cur + (32 + half * 8 + gid) * WS + kb);
            MMA2(ani, bn)
        }
        // h-part: A = h_in (words 32..63), B = hh @ cur+1920  (no mid-chunk sync!)
        #pragma unroll
        for (int ks = 0; ks < 4; ++ks) {
            const uint32_t* ap = s_xh + row0 * XHS + 32 + ks * 8;
            LOAD_A8(ap)
            const int kb = ks * 8 + 2 * tig;
            uint2 br = *(const uint2*)(cur + 1920 + (half * 8 + gid) * WS + kb);
            MMA2(ar, br)
            uint2 bz = *(const uint2*)(cur + 1920 + (16 + half * 8 + gid) * WS + kb);
            MMA2(az, bz)
            uint2 bn = *(const uint2*)(cur + 1920 + (32 + half * 8 + gid) * WS + kb);
            MMA2(anh, bn)
        }
        if (c == 3) { PAIR_BAR; }  // partner finished h_in reads before h writes
        #pragma unroll
        for (int s = 0; s < 2; ++s) {
            #pragma unroll
            for (int rb_ = 0; rb_ < 2; ++rb_) {
                int row = row0 + s * 16 + rb_ * 8;
                int j = c * 16 + half * 8 + 2 * tig;
                int e0 = rb_ * 2;
                float2 hp = u2f2(s_xh[row * XHS + 32 + (j >> 1)]);
                float r0_ = sig_(ar[s][e0]),     r1_ = sig_(ar[s][e0 + 1]);
                float z0_ = sig_(az[s][e0]),     z1_ = sig_(az[s][e0 + 1]);
                float n0_ = tanh_f(fmaf(r0_, anh[s][e0],     ani[s][e0]));
                float n1_ = tanh_f(fmaf(r1_, anh[s][e0 + 1], ani[s][e0 + 1]));
                float h0_ = fmaf(z0_, hp.x - n0_, n0_);
                float h1_ = fmaf(z1_, hp.y - n1_, n1_);
                if (c < 3) { hpark[c * 8 + s * 4 + e0] = h0_; hpark[c * 8 + s * 4 + e0 + 1] = h1_; }
                else s_xh[row * XHS + 32 + (j >> 1)] = h2u(h0_, h1_);
            }
        }
        if (c == 3) {
            #pragma unroll
            for (int cc = 0; cc < 3; ++cc)
                #pragma unroll
                for (int s = 0; s < 2; ++s)
                    #pragma unroll
                    for (int rb_ = 0; rb_ < 2; ++rb_) {
                        int row = row0 + s * 16 + rb_ * 8;
                        int j = cc * 16 + half * 8 + 2 * tig;
                        s_xh[row * XHS + 32 + (j >> 1)] =
                            h2u(hpark[cc * 8 + s * 4 + rb_ * 2],
                                hpark[cc * 8 + s * 4 + rb_ * 2 + 1]);
                    }
        }
        CP_WAIT0;
        __syncthreads();
    }

    // ---- h output (fp16 smem -> f32 gmem, coalesced) ----
    {
        float4* hout = (float4*)(out + (size_t)MTOT * 32);
        for (int i = t; i < TOK * 16; i += TPB) {
            int r = i >> 4, c = i & 15;
            uint2 w2 = *(const uint2*)(s_xh + r * XHS + 32 + 2 * c);
            float2 f0 = u2f2(w2.x), f1 = u2f2(w2.y);
            hout[(size_t)(base + r) * 16 + c] = make_float4(f0.x, f0.y, f1.x, f1.y);
        }
    }

    // ---- experts: E1+E2 staged together; 1 block sync + 1 pair bar per expert ----
    float fq[2][2][4];
    #pragma unroll
    for (int q = 0; q < 2; ++q)
        #pragma unroll
        for (int s = 0; s < 2; ++s)
            { fq[q][s][0] = fq[q][s][1] = fq[q][s][2] = fq[q][s][3] = 0.f; }
    float* eobase = out + (size_t)MTOT * 96;

    #pragma unroll 1
    for (int n = 0; n < 8; ++n) {
        uint32_t* cur = (n & 1) ? s_w : s_w + BUF1;   // E(0) in buf1 (staged in GRU c3)
        uint32_t* oth = (n & 1) ? s_w + BUF1 : s_w;
        if (n < 7) { stage_async(oth, g_wp + GW_E + (n + 1) * 3840, 3840, t); }
        CP_COMMIT;

        float acc1[4][2][4];
        #pragma unroll
        for (int nt = 0; nt < 4; ++nt) {
            int cb = n * 64 + half * 32 + nt * 8 + 2 * tig;
            float b0 = __ldg(e_b1 + cb), b1 = __ldg(e_b1 + cb + 1);
            #pragma unroll
            for (int s = 0; s < 2; ++s) {
                acc1[nt][s][0] = b0; acc1[nt][s][1] = b1;
                acc1[nt][s][2] = b0; acc1[nt][s][3] = b1;
            }
        }
        // E1: A = h (words 32..63), B @ cur
        #pragma unroll
        for (int ks = 0; ks < 4; ++ks) {
            const uint32_t* ap = s_xh + row0 * XHS + 32 + ks * 8;
            LOAD_A8(ap)
            const int kb = ks * 8 + 2 * tig;
            #pragma unroll
            for (int nt = 0; nt < 4; ++nt) {
                uint2 bv = *(const uint2*)(cur + (half * 32 + nt * 8 + gid) * WS + kb);
                MMA2(acc1[nt], bv)
            }
        }
        #pragma unroll
        for (int nt = 0; nt < 4; ++nt) {   // relu(h1) fp16 -> words 0..31 (pair-local rows)
            int wq = half * 16 + nt * 4 + tig;
            #pragma unroll
            for (int s = 0; s < 2; ++s) {
                int ra = row0 + s * 16, rb = ra + 8;
                s_xh[ra * XHS + wq] = h2u(fmaxf(acc1[nt][s][0], 0.f), fmaxf(acc1[nt][s][1], 0.f));
                s_xh[rb * XHS + wq] = h2u(fmaxf(acc1[nt][s][2], 0.f), fmaxf(acc1[nt][s][3], 0.f));
            }
        }
        PAIR_BAR;   // pair-local h1 handoff (E2 reads only this pair's rows)

        float acc2[2][2][4];
        #pragma unroll
        for (int nt = 0; nt < 2; ++nt) {
            int cb = n * 32 + half * 16 + nt * 8 + 2 * tig;
            float b0 = __ldg(e_b2 + cb), b1 = __ldg(e_b2 + cb + 1);
            #pragma unroll
            for (int s = 0; s < 2; ++s) {
                acc2[nt][s][0] = b0; acc2[nt][s][1] = b1;
                acc2[nt][s][2] = b0; acc2[nt][s][3] = b1;
            }
        }
        // E2: A = h1 (words 0..31), B @ cur+2560
        #pragma unroll
        for (int ks = 0; ks < 4; ++ks) {
            const uint32_t* ap = s_xh + row0 * XHS + ks * 8;
            LOAD_A8(ap)
            const int kb = ks * 8 + 2 * tig;
            #pragma unroll
            for (int nt = 0; nt < 2; ++nt) {
                uint2 bv = *(const uint2*)(cur + 2560 + (half * 16 + nt * 8 + gid) * WS + kb);
                MMA2(acc2[nt], bv)
            }
        }
        #pragma unroll
        for (int s = 0; s < 2; ++s) {
            int ra = row0 + s * 16, rb = ra + 8;
            float w0 = s_gate[ra * 9 + n], w1 = s_gate[rb * 9 + n];
            #pragma unroll
            for (int nt = 0; nt < 2; ++nt) {
                fq[nt][s][0] = fmaf(acc2[nt][s][0], w0, fq[nt][s][0]);
                fq[nt][s][1] = fmaf(acc2[nt][s][1], w0, fq[nt][s][1]);
                fq[nt][s][2] = fmaf(acc2[nt][s][2], w1, fq[nt][s][2]);
                fq[nt][s][3] = fmaf(acc2[nt][s][3], w1, fq[nt][s][3]);
                int c0 = n * 32 + half * 16 + nt * 8 + 2 * tig;
                *(float2*)(eobase + (size_t)(base + ra) * 256 + c0) =
                    make_float2(acc2[nt][s][0], acc2[nt][s][1]);
                *(float2*)(eobase + (size_t)(base + rb) * 256 + c0) =
                    make_float2(acc2[nt][s][2], acc2[nt][s][3]);
            }
        }
        CP_WAIT0;
        __syncthreads();   // buffer swap safety
    }

    // ---- final_q ----
    #pragma unroll
    for (int s = 0; s < 2; ++s) {
        int ra = row0 + s * 16, rb = ra + 8;
        #pragma unroll
        for (int nt = 0; nt < 2; ++nt) {
            int c0 = half * 16 + nt * 8 + 2 * tig;
            *(float2*)(out + (size_t)(base + ra) * 32 + c0) =
                make_float2(fq[nt][s][0] * 0.125f, fq[nt][s][1] * 0.125f);
            *(float2*)(out + (size_t)(base + rb) * 32 + c0) =
                make_float2(fq[nt][s][2] * 0.125f, fq[nt][s][3] * 0.125f);
        }
    }
}

extern "C" void kernel_launch(void* const* d_in, const int* in_sizes, int n_in,
                              void* d_out, int out_size) {
    (void)in_sizes; (void)n_in; (void)out_size;
    prep_pack<<<128, 256>>>(
        (const float*)d_in[2],  (const float*)d_in[12],
        (const float*)d_in[4],  (const float*)d_in[5],
        (const float*)d_in[8],  (const float*)d_in[10]);
    cudaFuncSetAttribute(msp_main, cudaFuncAttributeMaxDynamicSharedMemorySize, SMEMW * 4);
    msp_main<<<NBLK, TPB, SMEMW * 4>>>(
        (const float*)d_in[0],  (const float*)d_in[1],
        (const float*)d_in[3],
        (const float*)d_in[6],  (const float*)d_in[7],
        (const float*)d_in[9],  (const float*)d_in[11],
        (const float*)d_in[13],
        (float*)d_out);
}